// round 2
// baseline (speedup 1.0000x reference)
#include <cuda_runtime.h>
#include <math.h>

#define N_NODES 50000
#define FDIM    160
#define NMAX    50020   // N + S_EXTRA(20) padding rows
#define NEDGE   500000
#define DKDIM   64

// ---------------- static device scratch (no runtime allocation) ----------------
__device__ float g_X0 [NMAX * FDIM];   // concat(aft_rnn, static), rows >= N are zero
__device__ float g_H  [NMAX * FDIM];   // h = feats @ W for current layer
__device__ float g_T  [NMAX * FDIM];   // inner-layer output for 2-layer branches
__device__ float g_A1 [NMAX * FDIM];
__device__ float g_A2 [NMAX * FDIM];
__device__ float g_A3 [NMAX * FDIM];
__device__ float g_A4 [NMAX * FDIM];
__device__ float g_Ady[NMAX * FDIM];
__device__ float g_el [NMAX];
__device__ float g_er [NMAX];
__device__ float g_m  [NMAX];
__device__ float g_s  [NMAX];
__device__ float g_eb [NEDGE];
__device__ float g_exb[NEDGE];
__device__ float g_Q  [N_NODES * DKDIM];
__device__ float g_K  [N_NODES * 5 * DKDIM];

// ---------------- helpers ----------------
__device__ __forceinline__ float atomicMaxFloat(float* addr, float value) {
    // int-ordered trick: positives via signed atomicMax, negatives via unsigned atomicMin
    if (value >= 0.0f)
        return __int_as_float(atomicMax((int*)addr, __float_as_int(value)));
    else
        return __uint_as_float(atomicMin((unsigned int*)addr, __float_as_uint(value)));
}

__device__ __forceinline__ float warp_sum(float v) {
    #pragma unroll
    for (int o = 16; o > 0; o >>= 1) v += __shfl_xor_sync(0xffffffffu, v, o);
    return v;
}

// vectorized global reduction: 1 RED.V4 instead of 4 scalar REDs
__device__ __forceinline__ void red_add_v4(float* p, float x, float y, float z, float w) {
    asm volatile("red.global.add.v4.f32 [%0], {%1, %2, %3, %4};"
                 :: "l"(p), "f"(x), "f"(y), "f"(z), "f"(w) : "memory");
}

// ---------------- GEMM: C[n x NCOLS] = A[n x 160] @ B[160 x NCOLS] (+bias) ----------------
// block = 256 threads, tile 64 rows x NCOLS cols, K-chunks of 8 staged in smem.
template <int NCOLS>
__global__ void gemm_kernel(const float* __restrict__ A, const float* __restrict__ B,
                            const float* __restrict__ bias, float* __restrict__ C,
                            int n, int ldc) {
    constexpr int CJ = NCOLS / 16;
    __shared__ float As[8][65];       // padded to kill store bank conflicts
    __shared__ float Bs[8][NCOLS];

    const int tx = threadIdx.x & 15;
    const int ty = threadIdx.x >> 4;
    const int row0 = blockIdx.x * 64;

    float acc[4][CJ];
    #pragma unroll
    for (int i = 0; i < 4; i++)
        #pragma unroll
        for (int j = 0; j < CJ; j++) acc[i][j] = 0.0f;

    for (int k0 = 0; k0 < FDIM; k0 += 8) {
        // stage A (64x8), transposed into As[k][m]
        for (int idx = threadIdx.x; idx < 512; idx += 256) {
            int m = idx >> 3, k = idx & 7;
            int r = row0 + m;
            As[k][m] = (r < n) ? A[(size_t)r * FDIM + k0 + k] : 0.0f;
        }
        // stage B (8 x NCOLS)
        for (int idx = threadIdx.x; idx < 8 * NCOLS; idx += 256) {
            int k = idx / NCOLS, c = idx % NCOLS;
            Bs[k][c] = B[(size_t)(k0 + k) * NCOLS + c];
        }
        __syncthreads();
        #pragma unroll
        for (int k = 0; k < 8; k++) {
            float a[4], b[CJ];
            #pragma unroll
            for (int i = 0; i < 4; i++) a[i] = As[k][ty + 16 * i];
            #pragma unroll
            for (int j = 0; j < CJ; j++) b[j] = Bs[k][tx + 16 * j];
            #pragma unroll
            for (int i = 0; i < 4; i++)
                #pragma unroll
                for (int j = 0; j < CJ; j++) acc[i][j] += a[i] * b[j];
        }
        __syncthreads();
    }

    #pragma unroll
    for (int i = 0; i < 4; i++) {
        int r = row0 + ty + 16 * i;
        if (r < n) {
            #pragma unroll
            for (int j = 0; j < CJ; j++) {
                int c = tx + 16 * j;
                float v = acc[i][j];
                if (bias) v += bias[c];
                C[(size_t)r * ldc + c] = v;
            }
        }
    }
}

// ---------------- per-node / per-edge kernels ----------------
__global__ void concat_kernel(const float* __restrict__ aft, const float* __restrict__ sta) {
    int idx = blockIdx.x * blockDim.x + threadIdx.x;
    if (idx >= NMAX * FDIM) return;
    int nd = idx / FDIM, f = idx % FDIM;
    float v = 0.0f;
    if (nd < N_NODES) v = (f < 144) ? aft[nd * 144 + f] : sta[nd * 16 + (f - 144)];
    g_X0[idx] = v;
}

__global__ void zero_kernel(float* __restrict__ p, int count4) {
    int i = blockIdx.x * blockDim.x + threadIdx.x;
    if (i < count4) ((float4*)p)[i] = make_float4(0.f, 0.f, 0.f, 0.f);
}

__global__ void init_ms_kernel(int n) {
    int i = blockIdx.x * blockDim.x + threadIdx.x;
    if (i < n) { g_m[i] = -INFINITY; g_s[i] = 0.0f; }
}

__global__ void eldot_kernel(const float* __restrict__ al, const float* __restrict__ ar, int n) {
    int gid = blockIdx.x * blockDim.x + threadIdx.x;
    int w = gid >> 5;
    int lane = threadIdx.x & 31;
    if (w >= n) return;
    const float* h = g_H + (size_t)w * FDIM;
    float sl = 0.f, sr = 0.f;
    #pragma unroll
    for (int f = lane; f < FDIM; f += 32) {
        float v = h[f];
        sl += v * al[f];
        sr += v * ar[f];
    }
    sl = warp_sum(sl);
    sr = warp_sum(sr);
    if (lane == 0) { g_el[w] = sl; g_er[w] = sr; }
}

__global__ void edge_max_kernel(const int* __restrict__ src, const int* __restrict__ dst) {
    int i = blockIdx.x * blockDim.x + threadIdx.x;
    if (i >= NEDGE) return;
    int d = dst[i];
    float z = g_el[src[i]] + g_er[d];
    float e = (z > 0.f) ? z : 0.2f * z;   // leaky_relu slope 0.2
    g_eb[i] = e;
    atomicMaxFloat(&g_m[d], e);
}

__global__ void fix_m_kernel(int n) {
    int i = blockIdx.x * blockDim.x + threadIdx.x;
    if (i < n) {
        float v = g_m[i];
        if (!isfinite(v)) g_m[i] = 0.0f;
    }
}

__global__ void edge_expsum_kernel(const int* __restrict__ dst) {
    int i = blockIdx.x * blockDim.x + threadIdx.x;
    if (i >= NEDGE) return;
    int d = dst[i];
    float ex = expf(g_eb[i] - g_m[d]);
    g_exb[i] = ex;
    atomicAdd(&g_s[d], ex);
}

// one warp per edge: dest[dst] += alpha * h[src] via vectorized RED
__global__ void edge_scatter_kernel(const int* __restrict__ src, const int* __restrict__ dst,
                                    float* __restrict__ dest) {
    int gid = blockIdx.x * blockDim.x + threadIdx.x;
    int w = gid >> 5;
    int lane = threadIdx.x & 31;
    if (w >= NEDGE) return;
    int sN = src[w], d = dst[w];
    float alpha = g_exb[w] / fmaxf(g_s[d], 1e-9f);
    const float4* hs = (const float4*)(g_H + (size_t)sN * FDIM);
    float* od = dest + (size_t)d * FDIM;
    #pragma unroll
    for (int t = lane; t < FDIM / 4; t += 32) {
        float4 v = hs[t];
        red_add_v4(od + 4 * t, alpha * v.x, alpha * v.y, alpha * v.z, alpha * v.w);
    }
}

__global__ void bias_act_kernel(float* __restrict__ dest, const float* __restrict__ b, int n) {
    int idx = blockIdx.x * blockDim.x + threadIdx.x;
    if (idx >= n * FDIM) return;
    int f = idx % FDIM;
    float v = dest[idx] + b[f];
    dest[idx] = (v > 0.f) ? v : 0.01f * v;   // leaky_relu slope 0.01
}

// ---------------- final attention merge + classifier + log_softmax ----------------
__global__ void attn_kernel(const float* __restrict__ Wl, const float* __restrict__ bl,
                            float* __restrict__ out) {
    int gid = blockIdx.x * blockDim.x + threadIdx.x;
    int w = gid >> 5;
    int lane = threadIdx.x & 31;
    if (w >= N_NODES) return;

    const float* q = g_Q + (size_t)w * DKDIM;
    float q0 = q[lane], q1 = q[lane + 32];

    float logit[5];
    #pragma unroll
    for (int j = 0; j < 5; j++) {
        const float* kp = g_K + ((size_t)w * 5 + j) * DKDIM;
        float dsum = q0 * kp[lane] + q1 * kp[lane + 32];
        dsum = warp_sum(dsum);
        logit[j] = dsum * 0.125f;   // 1/sqrt(64)
    }

    float mx = logit[0];
    #pragma unroll
    for (int j = 1; j < 5; j++) mx = fmaxf(mx, logit[j]);
    float aw[5], asum = 0.f;
    #pragma unroll
    for (int j = 0; j < 5; j++) { aw[j] = expf(logit[j] - mx); asum += aw[j]; }
    float inv = 1.0f / asum;

    const float* xr = g_X0 + (size_t)w * FDIM;
    const float* Ap[5] = { g_A1 + (size_t)w * FDIM, g_A2 + (size_t)w * FDIM,
                           g_A3 + (size_t)w * FDIM, g_A4 + (size_t)w * FDIM,
                           g_Ady + (size_t)w * FDIM };
    float y0 = 0.f, y1 = 0.f;
    #pragma unroll
    for (int t = 0; t < 5; t++) {
        int f = lane + 32 * t;
        float mf = 0.f;
        #pragma unroll
        for (int j = 0; j < 5; j++) mf += aw[j] * Ap[j][f];
        mf *= inv;
        float xv = xr[f];
        y0 += xv * Wl[2 * f]     + mf * Wl[2 * (160 + f)];
        y1 += xv * Wl[2 * f + 1] + mf * Wl[2 * (160 + f) + 1];
    }
    y0 = warp_sum(y0);
    y1 = warp_sum(y1);
    if (lane == 0) {
        y0 += bl[0]; y1 += bl[1];
        float m2 = fmaxf(y0, y1);
        float lz = m2 + logf(expf(y0 - m2) + expf(y1 - m2));
        out[2 * w]     = y0 - lz;
        out[2 * w + 1] = y1 - lz;
    }
}

// ---------------- host orchestration ----------------
static inline int cdiv(int a, int b) { return (a + b - 1) / b; }

extern "C" void kernel_launch(void* const* d_in, const int* in_sizes, int n_in,
                              void* d_out, int out_size) {
    // Detect input ordering: dict order has edges at idx 2 (size 500000),
    // reference-signature order has gat_W at idx 2 (size 7*160*160 = 179200).
    bool sigOrder = (in_sizes[2] == 7 * FDIM * FDIM);
    int wbase = sigOrder ? 2 : 16;
    int ebase = sigOrder ? 12 : 2;

    const float* aft   = (const float*)d_in[0];
    const float* sta   = (const float*)d_in[1];
    const float* gat_W = (const float*)d_in[wbase + 0];
    const float* gat_al= (const float*)d_in[wbase + 1];
    const float* gat_ar= (const float*)d_in[wbase + 2];
    const float* gat_b = (const float*)d_in[wbase + 3];
    const float* Wq    = (const float*)d_in[wbase + 4];
    const float* bq    = (const float*)d_in[wbase + 5];
    const float* Wk    = (const float*)d_in[wbase + 6];
    const float* bk    = (const float*)d_in[wbase + 7];
    const float* Wl    = (const float*)d_in[wbase + 8];
    const float* bl    = (const float*)d_in[wbase + 9];
    const int* e[14];
    for (int i = 0; i < 14; i++) e[i] = (const int*)d_in[ebase + i];

    // resolve device scratch addresses
    void *pX0, *pT, *pA1, *pA2, *pA3, *pA4, *pAdy, *pQ, *pK, *pH;
    cudaGetSymbolAddress(&pX0, g_X0);
    cudaGetSymbolAddress(&pT,  g_T);
    cudaGetSymbolAddress(&pA1, g_A1);
    cudaGetSymbolAddress(&pA2, g_A2);
    cudaGetSymbolAddress(&pA3, g_A3);
    cudaGetSymbolAddress(&pA4, g_A4);
    cudaGetSymbolAddress(&pAdy,g_Ady);
    cudaGetSymbolAddress(&pQ,  g_Q);
    cudaGetSymbolAddress(&pK,  g_K);
    cudaGetSymbolAddress(&pH,  g_H);
    float* X0  = (float*)pX0;
    float* T   = (float*)pT;
    float* A1  = (float*)pA1;
    float* A2  = (float*)pA2;
    float* A3  = (float*)pA3;
    float* A4  = (float*)pA4;
    float* Ady = (float*)pAdy;
    float* Qb  = (float*)pQ;
    float* Kb  = (float*)pK;
    float* H   = (float*)pH;

    const int TPB = 256;

    // x = concat(aft_rnn, static); padded rows zeroed
    concat_kernel<<<cdiv(NMAX * FDIM, TPB), TPB>>>(aft, sta);

    // one GAT layer: dest = leaky_relu(GATConv(feats) + b, 0.01)
    auto layer = [&](const float* feats, int wi, const int* srcE, const int* dstE,
                     int n, float* dest) {
        gemm_kernel<160><<<cdiv(n, 64), TPB>>>(feats, gat_W + (size_t)wi * FDIM * FDIM,
                                               nullptr, H, n, FDIM);
        eldot_kernel<<<cdiv(n * 32, TPB), TPB>>>(gat_al + wi * FDIM, gat_ar + wi * FDIM, n);
        zero_kernel<<<cdiv(n * FDIM / 4, TPB), TPB>>>(dest, n * FDIM / 4);
        init_ms_kernel<<<cdiv(n, TPB), TPB>>>(n);
        edge_max_kernel<<<cdiv(NEDGE, TPB), TPB>>>(srcE, dstE);
        fix_m_kernel<<<cdiv(n, TPB), TPB>>>(n);
        edge_expsum_kernel<<<cdiv(NEDGE, TPB), TPB>>>(dstE);
        edge_scatter_kernel<<<cdiv(NEDGE * 32, TPB), TPB>>>(srcE, dstE, dest);
        bias_act_kernel<<<cdiv(n * FDIM, TPB), TPB>>>(dest, gat_b + wi * FDIM, n);
    };

    // branch layers (edge array order: dy, 1, 2, 3a, 3b, 4a, 4b)
    layer(X0, 0, e[0],  e[1],  N_NODES,      Ady);  // a_dy
    layer(X0, 1, e[2],  e[3],  N_NODES,      A1);   // a1
    layer(X0, 2, e[4],  e[5],  N_NODES,      A2);   // a2
    layer(X0, 3, e[6],  e[7],  N_NODES + 2,  T);    // g3 inner
    layer(T,  4, e[8],  e[9],  N_NODES + 2,  A3);   // a3 = g4(g3(...))
    layer(X0, 5, e[10], e[11], N_NODES + 20, T);    // g5 inner
    layer(T,  6, e[12], e[13], N_NODES + 20, A4);   // a4 = g6(g5(...))

    // Q and K projections
    gemm_kernel<64><<<cdiv(N_NODES, 64), TPB>>>(X0, Wq, bq, Qb, N_NODES, DKDIM);
    float* Abufs[5] = { A1, A2, A3, A4, Ady };      // stack order: a1,a2,a3,a4,a_dy
    for (int j = 0; j < 5; j++)
        gemm_kernel<64><<<cdiv(N_NODES, 64), TPB>>>(Abufs[j], Wk, bk,
                                                    Kb + j * DKDIM, N_NODES, 5 * DKDIM);

    // attention merge + classifier + log_softmax
    attn_kernel<<<cdiv(N_NODES * 32, TPB), TPB>>>(Wl, bl, (float*)d_out);
    (void)n_in; (void)out_size;
}

// round 5
// speedup vs baseline: 1.0504x; 1.0504x over previous
#include <cuda_runtime.h>
#include <math.h>

#define N_NODES 50000
#define FDIM    160
#define NMAX    50020   // N + S_EXTRA(20) padding rows
#define NEDGE   500000
#define DKDIM   64

// ---------------- static device scratch (no runtime allocation) ----------------
__device__ float g_X0 [NMAX * FDIM];   // concat(aft_rnn, static), rows >= N are zero
__device__ float g_H  [NMAX * FDIM];   // h = feats @ W for current layer
__device__ float g_T  [NMAX * FDIM];   // inner-layer output for 2-layer branches
__device__ float g_A1 [NMAX * FDIM];
__device__ float g_A2 [NMAX * FDIM];
__device__ float g_A3 [NMAX * FDIM];
__device__ float g_A4 [NMAX * FDIM];
__device__ float g_Ady[NMAX * FDIM];
__device__ float g_el [NMAX];
__device__ float g_er [NMAX];
__device__ int   g_off[NMAX + 1];      // CSR row offsets (by dst)
__device__ int   g_cnt[NMAX];          // histogram
__device__ int   g_cur[NMAX];          // fill cursors
__device__ int   g_ssrc[NEDGE];        // src ids sorted by dst
__device__ float g_Q  [N_NODES * DKDIM];
__device__ float g_K  [N_NODES * 5 * DKDIM];

// ---------------- helpers ----------------
__device__ __forceinline__ float warp_sum(float v) {
    #pragma unroll
    for (int o = 16; o > 0; o >>= 1) v += __shfl_xor_sync(0xffffffffu, v, o);
    return v;
}
__device__ __forceinline__ float warp_max(float v) {
    #pragma unroll
    for (int o = 16; o > 0; o >>= 1) v = fmaxf(v, __shfl_xor_sync(0xffffffffu, v, o));
    return v;
}

// ---------------- GEMM: C[n x NCOLS] = A[n x 160] @ B[160 x NCOLS] (+bias) ----------------
template <int NCOLS>
__global__ void gemm_kernel(const float* __restrict__ A, const float* __restrict__ B,
                            const float* __restrict__ bias, float* __restrict__ C,
                            int n, int ldc) {
    constexpr int CJ = NCOLS / 16;
    __shared__ float As[8][65];
    __shared__ float Bs[8][NCOLS];

    const int tx = threadIdx.x & 15;
    const int ty = threadIdx.x >> 4;
    const int row0 = blockIdx.x * 64;

    float acc[4][CJ];
    #pragma unroll
    for (int i = 0; i < 4; i++)
        #pragma unroll
        for (int j = 0; j < CJ; j++) acc[i][j] = 0.0f;

    for (int k0 = 0; k0 < FDIM; k0 += 8) {
        for (int idx = threadIdx.x; idx < 512; idx += 256) {
            int m = idx >> 3, k = idx & 7;
            int r = row0 + m;
            As[k][m] = (r < n) ? A[(size_t)r * FDIM + k0 + k] : 0.0f;
        }
        for (int idx = threadIdx.x; idx < 8 * NCOLS; idx += 256) {
            int k = idx / NCOLS, c = idx % NCOLS;
            Bs[k][c] = B[(size_t)(k0 + k) * NCOLS + c];
        }
        __syncthreads();
        #pragma unroll
        for (int k = 0; k < 8; k++) {
            float a[4], b[CJ];
            #pragma unroll
            for (int i = 0; i < 4; i++) a[i] = As[k][ty + 16 * i];
            #pragma unroll
            for (int j = 0; j < CJ; j++) b[j] = Bs[k][tx + 16 * j];
            #pragma unroll
            for (int i = 0; i < 4; i++)
                #pragma unroll
                for (int j = 0; j < CJ; j++) acc[i][j] += a[i] * b[j];
        }
        __syncthreads();
    }

    #pragma unroll
    for (int i = 0; i < 4; i++) {
        int r = row0 + ty + 16 * i;
        if (r < n) {
            #pragma unroll
            for (int j = 0; j < CJ; j++) {
                int c = tx + 16 * j;
                float v = acc[i][j];
                if (bias) v += bias[c];
                C[(size_t)r * ldc + c] = v;
            }
        }
    }
}

// ---------------- per-node / per-edge kernels ----------------
__global__ void concat_kernel(const float* __restrict__ aft, const float* __restrict__ sta) {
    int idx = blockIdx.x * blockDim.x + threadIdx.x;
    if (idx >= NMAX * FDIM) return;
    int nd = idx / FDIM, f = idx % FDIM;
    float v = 0.0f;
    if (nd < N_NODES) v = (f < 144) ? aft[nd * 144 + f] : sta[nd * 16 + (f - 144)];
    g_X0[idx] = v;
}

__global__ void eldot_kernel(const float* __restrict__ al, const float* __restrict__ ar, int n) {
    int gid = blockIdx.x * blockDim.x + threadIdx.x;
    int w = gid >> 5;
    int lane = threadIdx.x & 31;
    if (w >= n) return;
    const float* h = g_H + (size_t)w * FDIM;
    float sl = 0.f, sr = 0.f;
    #pragma unroll
    for (int f = lane; f < FDIM; f += 32) {
        float v = h[f];
        sl += v * al[f];
        sr += v * ar[f];
    }
    sl = warp_sum(sl);
    sr = warp_sum(sr);
    if (lane == 0) { g_el[w] = sl; g_er[w] = sr; }
}

// ---- CSR build: histogram -> scan -> fill ----
__global__ void zero_cnt_kernel(int n) {
    int i = blockIdx.x * blockDim.x + threadIdx.x;
    if (i < n) { g_cnt[i] = 0; g_cur[i] = 0; }
}

__global__ void hist_kernel(const int* __restrict__ dst) {
    int i = blockIdx.x * blockDim.x + threadIdx.x;
    if (i < NEDGE) atomicAdd(&g_cnt[dst[i]], 1);
}

// single-block exclusive scan over n counts -> g_off (and g_off[n] = total)
__global__ void scan_kernel(int n) {
    __shared__ int part[1024];
    const int t = threadIdx.x;
    const int C = (n + 1023) / 1024;
    const int base = t * C;
    int s = 0;
    for (int i = 0; i < C; i++) {
        int idx = base + i;
        if (idx < n) s += g_cnt[idx];
    }
    part[t] = s;
    __syncthreads();
    for (int o = 1; o < 1024; o <<= 1) {
        int u = (t >= o) ? part[t - o] : 0;
        __syncthreads();
        part[t] += u;
        __syncthreads();
    }
    int run = part[t] - s;   // exclusive prefix of this thread's chunk
    for (int i = 0; i < C; i++) {
        int idx = base + i;
        if (idx < n) { int c = g_cnt[idx]; g_off[idx] = run; run += c; }
    }
    if (t == 1023) g_off[n] = run;
}

__global__ void fill_kernel(const int* __restrict__ src, const int* __restrict__ dst) {
    int i = blockIdx.x * blockDim.x + threadIdx.x;
    if (i >= NEDGE) return;
    int d = dst[i];
    int slot = g_off[d] + atomicAdd(&g_cur[d], 1);
    g_ssrc[slot] = src[i];
}

// ---- fused edge-softmax + aggregation + bias + activation: one warp per node ----
// pass 1: online softmax (running max + rescaled sum); pass 2: weighted gather.
__global__ void node_gather_kernel(const float* __restrict__ b, float* __restrict__ dest, int n) {
    int gid = blockIdx.x * blockDim.x + threadIdx.x;
    int w = gid >> 5;
    int lane = threadIdx.x & 31;
    if (w >= n) return;

    const int start = g_off[w];
    const int end   = g_off[w + 1];
    const float er_d = g_er[w];

    // pass 1: per-lane online (m_i, s_i) over strided edges
    float mi = -INFINITY, si = 0.f;
    for (int j = start + lane; j < end; j += 32) {
        float z = g_el[g_ssrc[j]] + er_d;
        z = (z > 0.f) ? z : 0.2f * z;
        if (z > mi) {
            si = si * expf(mi - z) + 1.0f;   // first iter: 0*exp(-inf)=0 -> si=1
            mi = z;
        } else {
            si += expf(z - mi);
        }
    }
    float mx = warp_max(mi);
    if (!isfinite(mx)) mx = 0.0f;            // empty segment -> m=0 (matches ref)
    float s = warp_sum(si * expf(mi - mx));  // si=0 lanes contribute 0*exp(-inf)=0
    const float inv = 1.0f / fmaxf(s, 1e-9f);

    // pass 2: weighted feature accumulation (weights lane-parallel, broadcast by shfl)
    float acc0 = 0.f, acc1 = 0.f, acc2 = 0.f, acc3 = 0.f, acc4 = 0.f;
    for (int g0 = start; g0 < end; g0 += 32) {
        int j = g0 + lane;
        int sN = 0; float wgt = 0.f;
        if (j < end) {
            sN = g_ssrc[j];
            float z = g_el[sN] + er_d;
            z = (z > 0.f) ? z : 0.2f * z;
            wgt = expf(z - mx) * inv;
        }
        int cnt = min(32, end - g0);
        for (int k = 0; k < cnt; k++) {
            float wk = __shfl_sync(0xffffffffu, wgt, k);
            int   sk = __shfl_sync(0xffffffffu, sN,  k);
            const float* hp = g_H + (size_t)sk * FDIM;
            acc0 += wk * hp[lane];
            acc1 += wk * hp[lane + 32];
            acc2 += wk * hp[lane + 64];
            acc3 += wk * hp[lane + 96];
            acc4 += wk * hp[lane + 128];
        }
    }

    // epilogue: + bias, leaky_relu(0.01), single store
    float* od = dest + (size_t)w * FDIM;
    float v;
    v = acc0 + b[lane];       od[lane]       = (v > 0.f) ? v : 0.01f * v;
    v = acc1 + b[lane + 32];  od[lane + 32]  = (v > 0.f) ? v : 0.01f * v;
    v = acc2 + b[lane + 64];  od[lane + 64]  = (v > 0.f) ? v : 0.01f * v;
    v = acc3 + b[lane + 96];  od[lane + 96]  = (v > 0.f) ? v : 0.01f * v;
    v = acc4 + b[lane + 128]; od[lane + 128] = (v > 0.f) ? v : 0.01f * v;
}

// ---------------- final attention merge + classifier + log_softmax ----------------
__global__ void attn_kernel(const float* __restrict__ Wl, const float* __restrict__ bl,
                            float* __restrict__ out) {
    int gid = blockIdx.x * blockDim.x + threadIdx.x;
    int w = gid >> 5;
    int lane = threadIdx.x & 31;
    if (w >= N_NODES) return;

    const float* q = g_Q + (size_t)w * DKDIM;
    float q0 = q[lane], q1 = q[lane + 32];

    float logit[5];
    #pragma unroll
    for (int j = 0; j < 5; j++) {
        const float* kp = g_K + ((size_t)w * 5 + j) * DKDIM;
        float dsum = q0 * kp[lane] + q1 * kp[lane + 32];
        dsum = warp_sum(dsum);
        logit[j] = dsum * 0.125f;   // 1/sqrt(64)
    }

    float mx = logit[0];
    #pragma unroll
    for (int j = 1; j < 5; j++) mx = fmaxf(mx, logit[j]);
    float aw[5], asum = 0.f;
    #pragma unroll
    for (int j = 0; j < 5; j++) { aw[j] = expf(logit[j] - mx); asum += aw[j]; }
    float inv = 1.0f / asum;

    const float* xr = g_X0 + (size_t)w * FDIM;
    const float* Ap[5] = { g_A1 + (size_t)w * FDIM, g_A2 + (size_t)w * FDIM,
                           g_A3 + (size_t)w * FDIM, g_A4 + (size_t)w * FDIM,
                           g_Ady + (size_t)w * FDIM };
    float y0 = 0.f, y1 = 0.f;
    #pragma unroll
    for (int t = 0; t < 5; t++) {
        int f = lane + 32 * t;
        float mf = 0.f;
        #pragma unroll
        for (int j = 0; j < 5; j++) mf += aw[j] * Ap[j][f];
        mf *= inv;
        float xv = xr[f];
        y0 += xv * Wl[2 * f]     + mf * Wl[2 * (160 + f)];
        y1 += xv * Wl[2 * f + 1] + mf * Wl[2 * (160 + f) + 1];
    }
    y0 = warp_sum(y0);
    y1 = warp_sum(y1);
    if (lane == 0) {
        y0 += bl[0]; y1 += bl[1];
        float m2 = fmaxf(y0, y1);
        float lz = m2 + logf(expf(y0 - m2) + expf(y1 - m2));
        out[2 * w]     = y0 - lz;
        out[2 * w + 1] = y1 - lz;
    }
}

// ---------------- host orchestration ----------------
static inline int cdiv(int a, int b) { return (a + b - 1) / b; }

extern "C" void kernel_launch(void* const* d_in, const int* in_sizes, int n_in,
                              void* d_out, int out_size) {
    bool sigOrder = (in_sizes[2] == 7 * FDIM * FDIM);
    int wbase = sigOrder ? 2 : 16;
    int ebase = sigOrder ? 12 : 2;

    const float* aft   = (const float*)d_in[0];
    const float* sta   = (const float*)d_in[1];
    const float* gat_W = (const float*)d_in[wbase + 0];
    const float* gat_al= (const float*)d_in[wbase + 1];
    const float* gat_ar= (const float*)d_in[wbase + 2];
    const float* gat_b = (const float*)d_in[wbase + 3];
    const float* Wq    = (const float*)d_in[wbase + 4];
    const float* bq    = (const float*)d_in[wbase + 5];
    const float* Wk    = (const float*)d_in[wbase + 6];
    const float* bk    = (const float*)d_in[wbase + 7];
    const float* Wl    = (const float*)d_in[wbase + 8];
    const float* bl    = (const float*)d_in[wbase + 9];
    const int* e[14];
    for (int i = 0; i < 14; i++) e[i] = (const int*)d_in[ebase + i];

    void *pX0, *pT, *pA1, *pA2, *pA3, *pA4, *pAdy, *pQ, *pK, *pH;
    cudaGetSymbolAddress(&pX0, g_X0);
    cudaGetSymbolAddress(&pT,  g_T);
    cudaGetSymbolAddress(&pA1, g_A1);
    cudaGetSymbolAddress(&pA2, g_A2);
    cudaGetSymbolAddress(&pA3, g_A3);
    cudaGetSymbolAddress(&pA4, g_A4);
    cudaGetSymbolAddress(&pAdy,g_Ady);
    cudaGetSymbolAddress(&pQ,  g_Q);
    cudaGetSymbolAddress(&pK,  g_K);
    cudaGetSymbolAddress(&pH,  g_H);
    float* X0  = (float*)pX0;
    float* T   = (float*)pT;
    float* A1  = (float*)pA1;
    float* A2  = (float*)pA2;
    float* A3  = (float*)pA3;
    float* A4  = (float*)pA4;
    float* Ady = (float*)pAdy;
    float* Qb  = (float*)pQ;
    float* Kb  = (float*)pK;
    float* H   = (float*)pH;

    const int TPB = 256;

    concat_kernel<<<cdiv(NMAX * FDIM, TPB), TPB>>>(aft, sta);

    auto layer = [&](const float* feats, int wi, const int* srcE, const int* dstE,
                     int n, float* dest) {
        gemm_kernel<160><<<cdiv(n, 64), TPB>>>(feats, gat_W + (size_t)wi * FDIM * FDIM,
                                               nullptr, H, n, FDIM);
        eldot_kernel<<<cdiv(n * 32, TPB), TPB>>>(gat_al + wi * FDIM, gat_ar + wi * FDIM, n);
        zero_cnt_kernel<<<cdiv(n, TPB), TPB>>>(n);
        hist_kernel<<<cdiv(NEDGE, TPB), TPB>>>(dstE);
        scan_kernel<<<1, 1024>>>(n);
        fill_kernel<<<cdiv(NEDGE, TPB), TPB>>>(srcE, dstE);
        node_gather_kernel<<<cdiv(n * 32, TPB), TPB>>>(gat_b + wi * FDIM, dest, n);
    };

    // branch layers (edge array order: dy, 1, 2, 3a, 3b, 4a, 4b)
    layer(X0, 0, e[0],  e[1],  N_NODES,      Ady);  // a_dy
    layer(X0, 1, e[2],  e[3],  N_NODES,      A1);   // a1
    layer(X0, 2, e[4],  e[5],  N_NODES,      A2);   // a2
    layer(X0, 3, e[6],  e[7],  N_NODES + 2,  T);    // g3 inner
    layer(T,  4, e[8],  e[9],  N_NODES + 2,  A3);   // a3 = g4(g3(...))
    layer(X0, 5, e[10], e[11], N_NODES + 20, T);    // g5 inner
    layer(T,  6, e[12], e[13], N_NODES + 20, A4);   // a4 = g6(g5(...))

    // Q and K projections
    gemm_kernel<64><<<cdiv(N_NODES, 64), TPB>>>(X0, Wq, bq, Qb, N_NODES, DKDIM);
    float* Abufs[5] = { A1, A2, A3, A4, Ady };      // stack order: a1,a2,a3,a4,a_dy
    for (int j = 0; j < 5; j++)
        gemm_kernel<64><<<cdiv(N_NODES, 64), TPB>>>(Abufs[j], Wk, bk,
                                                    Kb + j * DKDIM, N_NODES, 5 * DKDIM);

    attn_kernel<<<cdiv(N_NODES * 32, TPB), TPB>>>(Wl, bl, (float*)d_out);
    (void)n_in; (void)out_size;
}

// round 6
// speedup vs baseline: 1.3004x; 1.2380x over previous
#include <cuda_runtime.h>
#include <math.h>

#define N_NODES 50000
#define FDIM    160
#define NMAX    50020   // N + S_EXTRA(20) padding rows
#define NEDGE   500000
#define DKDIM   64

// ---------------- static device scratch (no runtime allocation) ----------------
__device__ float g_X0 [NMAX * FDIM];   // concat(aft_rnn, static), rows >= N are zero
__device__ float g_H  [NMAX * FDIM];   // h = feats @ W for current layer
__device__ float g_T  [NMAX * FDIM];   // inner-layer output for 2-layer branches
__device__ float g_A1 [NMAX * FDIM];
__device__ float g_A2 [NMAX * FDIM];
__device__ float g_A3 [NMAX * FDIM];
__device__ float g_A4 [NMAX * FDIM];
__device__ float g_Ady[NMAX * FDIM];
__device__ float g_U  [N_NODES * FDIM];  // u = x @ (Wq Wk^T) + Wk bq
__device__ float g_M1 [FDIM * FDIM];     // Wq @ Wk^T
__device__ float g_v1 [FDIM];            // Wk @ bq
__device__ float g_el [NMAX];
__device__ float g_er [NMAX];
__device__ int   g_off[NMAX + 1];      // CSR row offsets (by dst)
__device__ int   g_cnt[NMAX];          // histogram
__device__ int   g_cur[NMAX];          // fill cursors
__device__ int   g_ssrc[NEDGE];        // src ids sorted by dst

// ---------------- helpers ----------------
__device__ __forceinline__ float warp_sum(float v) {
    #pragma unroll
    for (int o = 16; o > 0; o >>= 1) v += __shfl_xor_sync(0xffffffffu, v, o);
    return v;
}
__device__ __forceinline__ float warp_max(float v) {
    #pragma unroll
    for (int o = 16; o > 0; o >>= 1) v = fmaxf(v, __shfl_xor_sync(0xffffffffu, v, o));
    return v;
}

// ---------------- GEMM: C[n x 160] = A[n x 160] @ B[160 x 160] (+bias) ----------------
// Optional fused epilogue: el[r] = h[r]·al, er[r] = h[r]·ar (al != nullptr).
// block = 256 threads (16x16), tile 64 rows x 160 cols, K-chunks of 16.
__global__ void gemm_kernel(const float* __restrict__ A, const float* __restrict__ B,
                            const float* __restrict__ bias,
                            const float* __restrict__ al, const float* __restrict__ ar,
                            float* __restrict__ C,
                            float* __restrict__ el, float* __restrict__ er, int n) {
    constexpr int NCOLS = FDIM;
    constexpr int CJ = NCOLS / 16;   // 10
    __shared__ float As[16][65];     // [k][m], padded
    __shared__ float Bs[16][NCOLS];
    __shared__ float s_al[NCOLS], s_ar[NCOLS];

    const int tx = threadIdx.x & 15;
    const int ty = threadIdx.x >> 4;
    const int row0 = blockIdx.x * 64;

    if (al) {
        for (int i = threadIdx.x; i < NCOLS; i += 256) {
            s_al[i] = al[i];
            s_ar[i] = ar[i];
        }
    }

    float acc[4][CJ];
    #pragma unroll
    for (int i = 0; i < 4; i++)
        #pragma unroll
        for (int j = 0; j < CJ; j++) acc[i][j] = 0.0f;

    for (int k0 = 0; k0 < FDIM; k0 += 16) {
        // stage A (64x16), transposed into As[k][m]
        for (int idx = threadIdx.x; idx < 1024; idx += 256) {
            int m = idx >> 4, k = idx & 15;
            int r = row0 + m;
            As[k][m] = (r < n) ? A[(size_t)r * FDIM + k0 + k] : 0.0f;
        }
        // stage B (16 x NCOLS)
        for (int idx = threadIdx.x; idx < 16 * NCOLS; idx += 256) {
            int k = idx / NCOLS, c = idx % NCOLS;
            Bs[k][c] = B[(size_t)(k0 + k) * NCOLS + c];
        }
        __syncthreads();
        #pragma unroll
        for (int k = 0; k < 16; k++) {
            float a[4], b[CJ];
            #pragma unroll
            for (int i = 0; i < 4; i++) a[i] = As[k][ty + 16 * i];
            #pragma unroll
            for (int j = 0; j < CJ; j++) b[j] = Bs[k][tx + 16 * j];
            #pragma unroll
            for (int i = 0; i < 4; i++)
                #pragma unroll
                for (int j = 0; j < CJ; j++) acc[i][j] += a[i] * b[j];
        }
        __syncthreads();
    }

    #pragma unroll
    for (int i = 0; i < 4; i++) {
        int r = row0 + ty + 16 * i;
        if (r < n) {
            #pragma unroll
            for (int j = 0; j < CJ; j++) {
                int c = tx + 16 * j;
                float v = acc[i][j];
                if (bias) v += bias[c];
                C[(size_t)r * FDIM + c] = v;
            }
        }
    }

    // fused el/er epilogue: per row, partial dot over this thread's 10 cols,
    // then reduce across the 16 tx lanes (contiguous half-warp).
    if (al) {
        #pragma unroll
        for (int i = 0; i < 4; i++) {
            float pl = 0.f, pr = 0.f;
            #pragma unroll
            for (int j = 0; j < CJ; j++) {
                float v = acc[i][j];
                pl += v * s_al[tx + 16 * j];
                pr += v * s_ar[tx + 16 * j];
            }
            #pragma unroll
            for (int o = 8; o > 0; o >>= 1) {
                pl += __shfl_xor_sync(0xffffffffu, pl, o);
                pr += __shfl_xor_sync(0xffffffffu, pr, o);
            }
            int r = row0 + ty + 16 * i;
            if (tx == 0 && r < n) { el[r] = pl; er[r] = pr; }
        }
    }
}

// ---------------- per-node / per-edge kernels ----------------
__global__ void concat_kernel(const float* __restrict__ aft, const float* __restrict__ sta) {
    int idx = blockIdx.x * blockDim.x + threadIdx.x;
    if (idx >= NMAX * FDIM) return;
    int nd = idx / FDIM, f = idx % FDIM;
    float v = 0.0f;
    if (nd < N_NODES) v = (f < 144) ? aft[nd * 144 + f] : sta[nd * 16 + (f - 144)];
    g_X0[idx] = v;
}

// ---- CSR build: histogram -> scan -> fill ----
__global__ void zero_cnt_kernel(int n) {
    int i = blockIdx.x * blockDim.x + threadIdx.x;
    if (i < n) { g_cnt[i] = 0; g_cur[i] = 0; }
}

__global__ void hist_kernel(const int* __restrict__ dst) {
    int i = blockIdx.x * blockDim.x + threadIdx.x;
    if (i < NEDGE) atomicAdd(&g_cnt[dst[i]], 1);
}

// single-block exclusive scan over n counts -> g_off (and g_off[n] = total)
__global__ void scan_kernel(int n) {
    __shared__ int part[1024];
    const int t = threadIdx.x;
    const int C = (n + 1023) / 1024;
    const int base = t * C;
    int s = 0;
    for (int i = 0; i < C; i++) {
        int idx = base + i;
        if (idx < n) s += g_cnt[idx];
    }
    part[t] = s;
    __syncthreads();
    for (int o = 1; o < 1024; o <<= 1) {
        int u = (t >= o) ? part[t - o] : 0;
        __syncthreads();
        part[t] += u;
        __syncthreads();
    }
    int run = part[t] - s;   // exclusive prefix of this thread's chunk
    for (int i = 0; i < C; i++) {
        int idx = base + i;
        if (idx < n) { int c = g_cnt[idx]; g_off[idx] = run; run += c; }
    }
    if (t == 1023) g_off[n] = run;
}

__global__ void fill_kernel(const int* __restrict__ src, const int* __restrict__ dst) {
    int i = blockIdx.x * blockDim.x + threadIdx.x;
    if (i >= NEDGE) return;
    int d = dst[i];
    int slot = g_off[d] + atomicAdd(&g_cur[d], 1);
    g_ssrc[slot] = src[i];
}

// ---- fused edge-softmax + aggregation + bias + activation: one warp per node ----
__global__ void node_gather_kernel(const float* __restrict__ b, float* __restrict__ dest, int n) {
    int gid = blockIdx.x * blockDim.x + threadIdx.x;
    int w = gid >> 5;
    int lane = threadIdx.x & 31;
    if (w >= n) return;

    const int start = g_off[w];
    const int end   = g_off[w + 1];
    const float er_d = g_er[w];

    // pass 1: per-lane online (m_i, s_i) over strided edges
    float mi = -INFINITY, si = 0.f;
    for (int j = start + lane; j < end; j += 32) {
        float z = g_el[g_ssrc[j]] + er_d;
        z = (z > 0.f) ? z : 0.2f * z;
        if (z > mi) {
            si = si * expf(mi - z) + 1.0f;
            mi = z;
        } else {
            si += expf(z - mi);
        }
    }
    float mx = warp_max(mi);
    if (!isfinite(mx)) mx = 0.0f;            // empty segment -> m=0 (matches ref)
    float s = warp_sum(si * expf(mi - mx));
    const float inv = 1.0f / fmaxf(s, 1e-9f);

    // pass 2: weighted feature accumulation (weights lane-parallel, broadcast by shfl)
    float acc0 = 0.f, acc1 = 0.f, acc2 = 0.f, acc3 = 0.f, acc4 = 0.f;
    for (int g0 = start; g0 < end; g0 += 32) {
        int j = g0 + lane;
        int sN = 0; float wgt = 0.f;
        if (j < end) {
            sN = g_ssrc[j];
            float z = g_el[sN] + er_d;
            z = (z > 0.f) ? z : 0.2f * z;
            wgt = expf(z - mx) * inv;
        }
        int cnt = min(32, end - g0);
        for (int k = 0; k < cnt; k++) {
            float wk = __shfl_sync(0xffffffffu, wgt, k);
            int   sk = __shfl_sync(0xffffffffu, sN,  k);
            const float* hp = g_H + (size_t)sk * FDIM;
            acc0 += wk * hp[lane];
            acc1 += wk * hp[lane + 32];
            acc2 += wk * hp[lane + 64];
            acc3 += wk * hp[lane + 96];
            acc4 += wk * hp[lane + 128];
        }
    }

    float* od = dest + (size_t)w * FDIM;
    float v;
    v = acc0 + b[lane];       od[lane]       = (v > 0.f) ? v : 0.01f * v;
    v = acc1 + b[lane + 32];  od[lane + 32]  = (v > 0.f) ? v : 0.01f * v;
    v = acc2 + b[lane + 64];  od[lane + 64]  = (v > 0.f) ? v : 0.01f * v;
    v = acc3 + b[lane + 96];  od[lane + 96]  = (v > 0.f) ? v : 0.01f * v;
    v = acc4 + b[lane + 128]; od[lane + 128] = (v > 0.f) ? v : 0.01f * v;
}

// ---------------- precompute M1 = Wq @ Wk^T, v1 = Wk @ bq ----------------
__global__ void prep_m1_kernel(const float* __restrict__ Wq, const float* __restrict__ Wk,
                               const float* __restrict__ bq) {
    int idx = blockIdx.x * blockDim.x + threadIdx.x;
    if (idx < FDIM * FDIM) {
        int f = idx / FDIM, g = idx % FDIM;
        float s = 0.f;
        #pragma unroll 8
        for (int d = 0; d < DKDIM; d++) s += Wq[f * DKDIM + d] * Wk[g * DKDIM + d];
        g_M1[idx] = s;
    }
    if (idx < FDIM) {
        float s = 0.f;
        #pragma unroll 8
        for (int d = 0; d < DKDIM; d++) s += bq[d] * Wk[idx * DKDIM + d];
        g_v1[idx] = s;
    }
}

// ---------------- final attention merge + classifier + log_softmax ----------------
// logit_j = (u · A_j) / 8  (j-independent bias terms cancel in softmax)
__global__ void attn_kernel(const float* __restrict__ Wl, const float* __restrict__ bl,
                            float* __restrict__ out) {
    int gid = blockIdx.x * blockDim.x + threadIdx.x;
    int w = gid >> 5;
    int lane = threadIdx.x & 31;
    if (w >= N_NODES) return;

    const float* ur = g_U + (size_t)w * FDIM;
    float u[5];
    #pragma unroll
    for (int t = 0; t < 5; t++) u[t] = ur[lane + 32 * t];

    const float* Ap[5] = { g_A1 + (size_t)w * FDIM, g_A2 + (size_t)w * FDIM,
                           g_A3 + (size_t)w * FDIM, g_A4 + (size_t)w * FDIM,
                           g_Ady + (size_t)w * FDIM };
    float a[5][5];
    #pragma unroll
    for (int j = 0; j < 5; j++)
        #pragma unroll
        for (int t = 0; t < 5; t++) a[j][t] = Ap[j][lane + 32 * t];

    float logit[5];
    #pragma unroll
    for (int j = 0; j < 5; j++) {
        float p = 0.f;
        #pragma unroll
        for (int t = 0; t < 5; t++) p += u[t] * a[j][t];
        logit[j] = warp_sum(p) * 0.125f;   // 1/sqrt(64)
    }

    float mx = logit[0];
    #pragma unroll
    for (int j = 1; j < 5; j++) mx = fmaxf(mx, logit[j]);
    float aw[5], asum = 0.f;
    #pragma unroll
    for (int j = 0; j < 5; j++) { aw[j] = expf(logit[j] - mx); asum += aw[j]; }
    float inv = 1.0f / asum;

    const float* xr = g_X0 + (size_t)w * FDIM;
    float y0 = 0.f, y1 = 0.f;
    #pragma unroll
    for (int t = 0; t < 5; t++) {
        int f = lane + 32 * t;
        float mf = 0.f;
        #pragma unroll
        for (int j = 0; j < 5; j++) mf += aw[j] * a[j][t];
        mf *= inv;
        float xv = xr[f];
        y0 += xv * Wl[2 * f]     + mf * Wl[2 * (160 + f)];
        y1 += xv * Wl[2 * f + 1] + mf * Wl[2 * (160 + f) + 1];
    }
    y0 = warp_sum(y0);
    y1 = warp_sum(y1);
    if (lane == 0) {
        y0 += bl[0]; y1 += bl[1];
        float m2 = fmaxf(y0, y1);
        float lz = m2 + logf(expf(y0 - m2) + expf(y1 - m2));
        out[2 * w]     = y0 - lz;
        out[2 * w + 1] = y1 - lz;
    }
}

// ---------------- host orchestration ----------------
static inline int cdiv(int a, int b) { return (a + b - 1) / b; }

extern "C" void kernel_launch(void* const* d_in, const int* in_sizes, int n_in,
                              void* d_out, int out_size) {
    bool sigOrder = (in_sizes[2] == 7 * FDIM * FDIM);
    int wbase = sigOrder ? 2 : 16;
    int ebase = sigOrder ? 12 : 2;

    const float* aft   = (const float*)d_in[0];
    const float* sta   = (const float*)d_in[1];
    const float* gat_W = (const float*)d_in[wbase + 0];
    const float* gat_al= (const float*)d_in[wbase + 1];
    const float* gat_ar= (const float*)d_in[wbase + 2];
    const float* gat_b = (const float*)d_in[wbase + 3];
    const float* Wq    = (const float*)d_in[wbase + 4];
    const float* bq    = (const float*)d_in[wbase + 5];
    const float* Wk    = (const float*)d_in[wbase + 6];
    // d_in[wbase+7] = bk: j-independent contribution cancels in softmax
    const float* Wl    = (const float*)d_in[wbase + 8];
    const float* bl    = (const float*)d_in[wbase + 9];
    const int* e[14];
    for (int i = 0; i < 14; i++) e[i] = (const int*)d_in[ebase + i];

    void *pX0, *pT, *pA1, *pA2, *pA3, *pA4, *pAdy, *pU, *pM1, *pV1, *pH, *pEl, *pEr;
    cudaGetSymbolAddress(&pX0, g_X0);
    cudaGetSymbolAddress(&pT,  g_T);
    cudaGetSymbolAddress(&pA1, g_A1);
    cudaGetSymbolAddress(&pA2, g_A2);
    cudaGetSymbolAddress(&pA3, g_A3);
    cudaGetSymbolAddress(&pA4, g_A4);
    cudaGetSymbolAddress(&pAdy,g_Ady);
    cudaGetSymbolAddress(&pU,  g_U);
    cudaGetSymbolAddress(&pM1, g_M1);
    cudaGetSymbolAddress(&pV1, g_v1);
    cudaGetSymbolAddress(&pH,  g_H);
    cudaGetSymbolAddress(&pEl, g_el);
    cudaGetSymbolAddress(&pEr, g_er);
    float* X0  = (float*)pX0;
    float* T   = (float*)pT;
    float* A1  = (float*)pA1;
    float* A2  = (float*)pA2;
    float* A3  = (float*)pA3;
    float* A4  = (float*)pA4;
    float* Ady = (float*)pAdy;
    float* Ub  = (float*)pU;
    float* M1  = (float*)pM1;
    float* V1  = (float*)pV1;
    float* H   = (float*)pH;
    float* El  = (float*)pEl;
    float* Er  = (float*)pEr;

    const int TPB = 256;

    concat_kernel<<<cdiv(NMAX * FDIM, TPB), TPB>>>(aft, sta);   // launch 0

    // per-layer: CSR build first so launch index 5 (ncu -s 5 -c 1) = gemm_kernel
    auto layer = [&](const float* feats, int wi, const int* srcE, const int* dstE,
                     int n, float* dest) {
        zero_cnt_kernel<<<cdiv(n, TPB), TPB>>>(n);
        hist_kernel<<<cdiv(NEDGE, TPB), TPB>>>(dstE);
        scan_kernel<<<1, 1024>>>(n);
        fill_kernel<<<cdiv(NEDGE, TPB), TPB>>>(srcE, dstE);
        gemm_kernel<<<cdiv(n, 64), TPB>>>(feats, gat_W + (size_t)wi * FDIM * FDIM,
                                          nullptr, gat_al + wi * FDIM, gat_ar + wi * FDIM,
                                          H, El, Er, n);
        node_gather_kernel<<<cdiv(n * 32, TPB), TPB>>>(gat_b + wi * FDIM, dest, n);
    };

    // branch layers (edge array order: dy, 1, 2, 3a, 3b, 4a, 4b)
    layer(X0, 0, e[0],  e[1],  N_NODES,      Ady);  // a_dy
    layer(X0, 1, e[2],  e[3],  N_NODES,      A1);   // a1
    layer(X0, 2, e[4],  e[5],  N_NODES,      A2);   // a2
    layer(X0, 3, e[6],  e[7],  N_NODES + 2,  T);    // g3 inner
    layer(T,  4, e[8],  e[9],  N_NODES + 2,  A3);   // a3 = g4(g3(...))
    layer(X0, 5, e[10], e[11], N_NODES + 20, T);    // g5 inner
    layer(T,  6, e[12], e[13], N_NODES + 20, A4);   // a4 = g6(g5(...))

    // u = x @ (Wq Wk^T) + Wk bq  (replaces Q and all 5 K projections)
    prep_m1_kernel<<<cdiv(FDIM * FDIM, TPB), TPB>>>(Wq, Wk, bq);
    gemm_kernel<<<cdiv(N_NODES, 64), TPB>>>(X0, M1, V1, nullptr, nullptr,
                                            Ub, nullptr, nullptr, N_NODES);

    attn_kernel<<<cdiv(N_NODES * 32, TPB), TPB>>>(Wl, bl, (float*)d_out);
    (void)n_in; (void)out_size;
}

// round 10
// speedup vs baseline: 1.5783x; 1.2137x over previous
#include <cuda_runtime.h>
#include <math.h>

#define N_NODES 50000
#define FDIM    160
#define NMAX    50020   // N + S_EXTRA(20) padding rows; divisible by 4
#define NEDGE   500000
#define DKDIM   64
#define NGRAPH  7
#define OFFSTR  (NMAX + 4)   // per-graph offset stride, multiple of 4 ints (16B)

// ---------------- static device scratch (no runtime allocation) ----------------
__device__ float g_X0 [NMAX * FDIM];
__device__ float g_H  [NMAX * FDIM];
__device__ float g_T  [NMAX * FDIM];
__device__ float g_A1 [NMAX * FDIM];
__device__ float g_A2 [NMAX * FDIM];
__device__ float g_A3 [NMAX * FDIM];
__device__ float g_A4 [NMAX * FDIM];
__device__ float g_Ady[NMAX * FDIM];
__device__ float g_U  [N_NODES * FDIM];  // u = x @ (Wq Wk^T) + Wk bq
__device__ float g_M1 [FDIM * FDIM];
__device__ float g_v1 [FDIM];
__device__ float g_el [NMAX];
__device__ float g_er [NMAX];
__device__ __align__(16) int g_cntB [NGRAPH * NMAX];    // per-graph histogram
__device__ __align__(16) int g_curB [NGRAPH * NMAX];    // per-graph fill cursors
__device__ __align__(16) int g_offB [NGRAPH * OFFSTR];  // per-graph CSR offsets (padded stride)
__device__ int   g_ssrcB[NGRAPH * NEDGE];               // per-graph src sorted by dst

struct EdgePtrs { const int* src[NGRAPH]; const int* dst[NGRAPH]; };

// ---------------- helpers ----------------
__device__ __forceinline__ float warp_sum(float v) {
    #pragma unroll
    for (int o = 16; o > 0; o >>= 1) v += __shfl_xor_sync(0xffffffffu, v, o);
    return v;
}
__device__ __forceinline__ float warp_max(float v) {
    #pragma unroll
    for (int o = 16; o > 0; o >>= 1) v = fmaxf(v, __shfl_xor_sync(0xffffffffu, v, o));
    return v;
}

// ---------------- batched CSR build ----------------
__global__ void batched_zero_kernel() {
    int i = blockIdx.x * blockDim.x + threadIdx.x;
    int n4 = NGRAPH * NMAX / 4;
    if (i < n4) {
        ((int4*)g_cntB)[i] = make_int4(0, 0, 0, 0);
        ((int4*)g_curB)[i] = make_int4(0, 0, 0, 0);
    }
}

__global__ void batched_hist_kernel(EdgePtrs ep) {
    int i = blockIdx.x * blockDim.x + threadIdx.x;
    if (i >= NGRAPH * NEDGE) return;
    int g = i / NEDGE, j = i - g * NEDGE;
    atomicAdd(&g_cntB[g * NMAX + ep.dst[g][j]], 1);
}

// one block per graph; int4-vectorized two-pass scan over NMAX counts
__global__ void batched_scan_kernel() {
    const int b = blockIdx.x;
    const int t = threadIdx.x;
    const int* cnt = g_cntB + b * NMAX;      // NMAX ints = 16B multiple: int4-safe
    int* off = g_offB + b * OFFSTR;          // OFFSTR ints = 16B multiple: int4-safe
    const int n4 = NMAX / 4;                 // 12505
    const int C4 = (n4 + 1023) / 1024;       // 13
    __shared__ int part[1024];

    // pass 1: per-thread chunk sum (vectorized)
    int s = 0;
    for (int i = 0; i < C4; i++) {
        int idx = t * C4 + i;
        if (idx < n4) {
            int4 v = ((const int4*)cnt)[idx];
            s += v.x + v.y + v.z + v.w;
        }
    }
    part[t] = s;
    __syncthreads();
    for (int o = 1; o < 1024; o <<= 1) {
        int u = (t >= o) ? part[t - o] : 0;
        __syncthreads();
        part[t] += u;
        __syncthreads();
    }
    int run = part[t] - s;   // exclusive prefix of this thread's chunk

    // pass 2: reload (L1-hot) and emit exclusive offsets (vectorized stores)
    for (int i = 0; i < C4; i++) {
        int idx = t * C4 + i;
        if (idx < n4) {
            int4 v = ((const int4*)cnt)[idx];
            int4 o;
            o.x = run; run += v.x;
            o.y = run; run += v.y;
            o.z = run; run += v.z;
            o.w = run; run += v.w;
            ((int4*)off)[idx] = o;
        }
    }
    if (t == 1023) off[NMAX] = run;
}

__global__ void batched_fill_kernel(EdgePtrs ep) {
    int i = blockIdx.x * blockDim.x + threadIdx.x;
    if (i >= NGRAPH * NEDGE) return;
    int g = i / NEDGE, j = i - g * NEDGE;
    int d = ep.dst[g][j];
    int slot = g_offB[g * OFFSTR + d] + atomicAdd(&g_curB[g * NMAX + d], 1);
    g_ssrcB[g * NEDGE + slot] = ep.src[g][j];
}

// ---------------- GEMM: C[n x 160] = A[n x 160] @ B[160 x 160] (+bias) ----------------
// Optional fused epilogue: el[r] = h[r]·al, er[r] = h[r]·ar (al != nullptr).
__global__ void gemm_kernel(const float* __restrict__ A, const float* __restrict__ B,
                            const float* __restrict__ bias,
                            const float* __restrict__ al, const float* __restrict__ ar,
                            float* __restrict__ C,
                            float* __restrict__ el, float* __restrict__ er, int n) {
    constexpr int NCOLS = FDIM;
    constexpr int CJ = NCOLS / 16;   // 10
    __shared__ float As[16][65];
    __shared__ float Bs[16][NCOLS];
    __shared__ float s_al[NCOLS], s_ar[NCOLS];

    const int tx = threadIdx.x & 15;
    const int ty = threadIdx.x >> 4;
    const int row0 = blockIdx.x * 64;

    if (al) {
        for (int i = threadIdx.x; i < NCOLS; i += 256) {
            s_al[i] = al[i];
            s_ar[i] = ar[i];
        }
    }

    float acc[4][CJ];
    #pragma unroll
    for (int i = 0; i < 4; i++)
        #pragma unroll
        for (int j = 0; j < CJ; j++) acc[i][j] = 0.0f;

    for (int k0 = 0; k0 < FDIM; k0 += 16) {
        for (int idx = threadIdx.x; idx < 1024; idx += 256) {
            int m = idx >> 4, k = idx & 15;
            int r = row0 + m;
            As[k][m] = (r < n) ? A[(size_t)r * FDIM + k0 + k] : 0.0f;
        }
        for (int idx = threadIdx.x; idx < 16 * NCOLS; idx += 256) {
            int k = idx / NCOLS, c = idx % NCOLS;
            Bs[k][c] = B[(size_t)(k0 + k) * NCOLS + c];
        }
        __syncthreads();
        #pragma unroll
        for (int k = 0; k < 16; k++) {
            float a[4], b[CJ];
            #pragma unroll
            for (int i = 0; i < 4; i++) a[i] = As[k][ty + 16 * i];
            #pragma unroll
            for (int j = 0; j < CJ; j++) b[j] = Bs[k][tx + 16 * j];
            #pragma unroll
            for (int i = 0; i < 4; i++)
                #pragma unroll
                for (int j = 0; j < CJ; j++) acc[i][j] += a[i] * b[j];
        }
        __syncthreads();
    }

    #pragma unroll
    for (int i = 0; i < 4; i++) {
        int r = row0 + ty + 16 * i;
        if (r < n) {
            #pragma unroll
            for (int j = 0; j < CJ; j++) {
                int c = tx + 16 * j;
                float v = acc[i][j];
                if (bias) v += bias[c];
                C[(size_t)r * FDIM + c] = v;
            }
        }
    }

    if (al) {
        #pragma unroll
        for (int i = 0; i < 4; i++) {
            float pl = 0.f, pr = 0.f;
            #pragma unroll
            for (int j = 0; j < CJ; j++) {
                float v = acc[i][j];
                pl += v * s_al[tx + 16 * j];
                pr += v * s_ar[tx + 16 * j];
            }
            #pragma unroll
            for (int o = 8; o > 0; o >>= 1) {
                pl += __shfl_xor_sync(0xffffffffu, pl, o);
                pr += __shfl_xor_sync(0xffffffffu, pr, o);
            }
            int r = row0 + ty + 16 * i;
            if (tx == 0 && r < n) { el[r] = pl; er[r] = pr; }
        }
    }
}

// ---------------- per-node kernels ----------------
__global__ void concat_kernel(const float* __restrict__ aft, const float* __restrict__ sta) {
    int idx = blockIdx.x * blockDim.x + threadIdx.x;
    if (idx >= NMAX * FDIM) return;
    int nd = idx / FDIM, f = idx % FDIM;
    float v = 0.0f;
    if (nd < N_NODES) v = (f < 144) ? aft[nd * 144 + f] : sta[nd * 16 + (f - 144)];
    g_X0[idx] = v;
}

// ---- fused edge-softmax + aggregation + bias + activation: one warp per node ----
__global__ void node_gather_kernel(const float* __restrict__ b, float* __restrict__ dest,
                                   int n, int gi) {
    int gid = blockIdx.x * blockDim.x + threadIdx.x;
    int w = gid >> 5;
    int lane = threadIdx.x & 31;
    if (w >= n) return;

    const int* off  = g_offB  + gi * OFFSTR;
    const int* ssrc = g_ssrcB + gi * NEDGE;
    const int start = off[w];
    const int end   = off[w + 1];
    const float er_d = g_er[w];

    // pass 1: per-lane online (m_i, s_i) over strided edges
    float mi = -INFINITY, si = 0.f;
    for (int j = start + lane; j < end; j += 32) {
        float z = g_el[ssrc[j]] + er_d;
        z = (z > 0.f) ? z : 0.2f * z;
        if (z > mi) {
            si = si * expf(mi - z) + 1.0f;
            mi = z;
        } else {
            si += expf(z - mi);
        }
    }
    float mx = warp_max(mi);
    if (!isfinite(mx)) mx = 0.0f;
    float s = warp_sum(si * expf(mi - mx));
    const float inv = 1.0f / fmaxf(s, 1e-9f);

    // pass 2: weighted feature accumulation
    float acc0 = 0.f, acc1 = 0.f, acc2 = 0.f, acc3 = 0.f, acc4 = 0.f;
    for (int g0 = start; g0 < end; g0 += 32) {
        int j = g0 + lane;
        int sN = 0; float wgt = 0.f;
        if (j < end) {
            sN = ssrc[j];
            float z = g_el[sN] + er_d;
            z = (z > 0.f) ? z : 0.2f * z;
            wgt = expf(z - mx) * inv;
        }
        int cnt = min(32, end - g0);
        for (int k = 0; k < cnt; k++) {
            float wk = __shfl_sync(0xffffffffu, wgt, k);
            int   sk = __shfl_sync(0xffffffffu, sN,  k);
            const float* hp = g_H + (size_t)sk * FDIM;
            acc0 += wk * hp[lane];
            acc1 += wk * hp[lane + 32];
            acc2 += wk * hp[lane + 64];
            acc3 += wk * hp[lane + 96];
            acc4 += wk * hp[lane + 128];
        }
    }

    float* od = dest + (size_t)w * FDIM;
    float v;
    v = acc0 + b[lane];       od[lane]       = (v > 0.f) ? v : 0.01f * v;
    v = acc1 + b[lane + 32];  od[lane + 32]  = (v > 0.f) ? v : 0.01f * v;
    v = acc2 + b[lane + 64];  od[lane + 64]  = (v > 0.f) ? v : 0.01f * v;
    v = acc3 + b[lane + 96];  od[lane + 96]  = (v > 0.f) ? v : 0.01f * v;
    v = acc4 + b[lane + 128]; od[lane + 128] = (v > 0.f) ? v : 0.01f * v;
}

// ---------------- precompute M1 = Wq @ Wk^T, v1 = Wk @ bq ----------------
__global__ void prep_m1_kernel(const float* __restrict__ Wq, const float* __restrict__ Wk,
                               const float* __restrict__ bq) {
    int idx = blockIdx.x * blockDim.x + threadIdx.x;
    if (idx < FDIM * FDIM) {
        int f = idx / FDIM, g = idx % FDIM;
        float s = 0.f;
        #pragma unroll 8
        for (int d = 0; d < DKDIM; d++) s += Wq[f * DKDIM + d] * Wk[g * DKDIM + d];
        g_M1[idx] = s;
    }
    if (idx < FDIM) {
        float s = 0.f;
        #pragma unroll 8
        for (int d = 0; d < DKDIM; d++) s += bq[d] * Wk[idx * DKDIM + d];
        g_v1[idx] = s;
    }
}

// ---------------- final attention merge + classifier + log_softmax ----------------
__global__ void attn_kernel(const float* __restrict__ Wl, const float* __restrict__ bl,
                            float* __restrict__ out) {
    int gid = blockIdx.x * blockDim.x + threadIdx.x;
    int w = gid >> 5;
    int lane = threadIdx.x & 31;
    if (w >= N_NODES) return;

    const float* ur = g_U + (size_t)w * FDIM;
    float u[5];
    #pragma unroll
    for (int t = 0; t < 5; t++) u[t] = ur[lane + 32 * t];

    const float* Ap[5] = { g_A1 + (size_t)w * FDIM, g_A2 + (size_t)w * FDIM,
                           g_A3 + (size_t)w * FDIM, g_A4 + (size_t)w * FDIM,
                           g_Ady + (size_t)w * FDIM };
    float a[5][5];
    #pragma unroll
    for (int j = 0; j < 5; j++)
        #pragma unroll
        for (int t = 0; t < 5; t++) a[j][t] = Ap[j][lane + 32 * t];

    float logit[5];
    #pragma unroll
    for (int j = 0; j < 5; j++) {
        float p = 0.f;
        #pragma unroll
        for (int t = 0; t < 5; t++) p += u[t] * a[j][t];
        logit[j] = warp_sum(p) * 0.125f;
    }

    float mx = logit[0];
    #pragma unroll
    for (int j = 1; j < 5; j++) mx = fmaxf(mx, logit[j]);
    float aw[5], asum = 0.f;
    #pragma unroll
    for (int j = 0; j < 5; j++) { aw[j] = expf(logit[j] - mx); asum += aw[j]; }
    float inv = 1.0f / asum;

    const float* xr = g_X0 + (size_t)w * FDIM;
    float y0 = 0.f, y1 = 0.f;
    #pragma unroll
    for (int t = 0; t < 5; t++) {
        int f = lane + 32 * t;
        float mf = 0.f;
        #pragma unroll
        for (int j = 0; j < 5; j++) mf += aw[j] * a[j][t];
        mf *= inv;
        float xv = xr[f];
        y0 += xv * Wl[2 * f]     + mf * Wl[2 * (160 + f)];
        y1 += xv * Wl[2 * f + 1] + mf * Wl[2 * (160 + f) + 1];
    }
    y0 = warp_sum(y0);
    y1 = warp_sum(y1);
    if (lane == 0) {
        y0 += bl[0]; y1 += bl[1];
        float m2 = fmaxf(y0, y1);
        float lz = m2 + logf(expf(y0 - m2) + expf(y1 - m2));
        out[2 * w]     = y0 - lz;
        out[2 * w + 1] = y1 - lz;
    }
}

// ---------------- host orchestration ----------------
static inline int cdiv(int a, int b) { return (a + b - 1) / b; }

extern "C" void kernel_launch(void* const* d_in, const int* in_sizes, int n_in,
                              void* d_out, int out_size) {
    bool sigOrder = (in_sizes[2] == 7 * FDIM * FDIM);
    int wbase = sigOrder ? 2 : 16;
    int ebase = sigOrder ? 12 : 2;

    const float* aft   = (const float*)d_in[0];
    const float* sta   = (const float*)d_in[1];
    const float* gat_W = (const float*)d_in[wbase + 0];
    const float* gat_al= (const float*)d_in[wbase + 1];
    const float* gat_ar= (const float*)d_in[wbase + 2];
    const float* gat_b = (const float*)d_in[wbase + 3];
    const float* Wq    = (const float*)d_in[wbase + 4];
    const float* bq    = (const float*)d_in[wbase + 5];
    const float* Wk    = (const float*)d_in[wbase + 6];
    const float* Wl    = (const float*)d_in[wbase + 8];
    const float* bl    = (const float*)d_in[wbase + 9];
    const int* e[14];
    for (int i = 0; i < 14; i++) e[i] = (const int*)d_in[ebase + i];

    void *pX0, *pT, *pA1, *pA2, *pA3, *pA4, *pAdy, *pU, *pM1, *pV1, *pH, *pEl, *pEr;
    cudaGetSymbolAddress(&pX0, g_X0);
    cudaGetSymbolAddress(&pT,  g_T);
    cudaGetSymbolAddress(&pA1, g_A1);
    cudaGetSymbolAddress(&pA2, g_A2);
    cudaGetSymbolAddress(&pA3, g_A3);
    cudaGetSymbolAddress(&pA4, g_A4);
    cudaGetSymbolAddress(&pAdy,g_Ady);
    cudaGetSymbolAddress(&pU,  g_U);
    cudaGetSymbolAddress(&pM1, g_M1);
    cudaGetSymbolAddress(&pV1, g_v1);
    cudaGetSymbolAddress(&pH,  g_H);
    cudaGetSymbolAddress(&pEl, g_el);
    cudaGetSymbolAddress(&pEr, g_er);
    float* X0  = (float*)pX0;
    float* T   = (float*)pT;
    float* A1  = (float*)pA1;
    float* A2  = (float*)pA2;
    float* A3  = (float*)pA3;
    float* A4  = (float*)pA4;
    float* Ady = (float*)pAdy;
    float* Ub  = (float*)pU;
    float* M1  = (float*)pM1;
    float* V1  = (float*)pV1;
    float* H   = (float*)pH;
    float* El  = (float*)pEl;
    float* Er  = (float*)pEr;

    const int TPB = 256;

    // batched CSR build for all 7 graphs up front (edge order: dy,1,2,3a,3b,4a,4b)
    EdgePtrs ep;
    for (int g = 0; g < NGRAPH; g++) { ep.src[g] = e[2 * g]; ep.dst[g] = e[2 * g + 1]; }
    batched_zero_kernel<<<cdiv(NGRAPH * NMAX / 4, TPB), TPB>>>();          // launch 0
    batched_hist_kernel<<<cdiv(NGRAPH * NEDGE, TPB), TPB>>>(ep);           // launch 1
    batched_scan_kernel<<<NGRAPH, 1024>>>();                               // launch 2
    batched_fill_kernel<<<cdiv(NGRAPH * NEDGE, TPB), TPB>>>(ep);           // launch 3

    concat_kernel<<<cdiv(NMAX * FDIM, TPB), TPB>>>(aft, sta);              // launch 4

    auto layer = [&](const float* feats, int wi, int gi, int n, float* dest) {
        gemm_kernel<<<cdiv(n, 64), TPB>>>(feats, gat_W + (size_t)wi * FDIM * FDIM,
                                          nullptr, gat_al + wi * FDIM, gat_ar + wi * FDIM,
                                          H, El, Er, n);                   // first layer: launch 5
        node_gather_kernel<<<cdiv(n * 32, TPB), TPB>>>(gat_b + wi * FDIM, dest, n, gi);
    };

    layer(X0, 0, 0, N_NODES,      Ady);  // a_dy
    layer(X0, 1, 1, N_NODES,      A1);   // a1
    layer(X0, 2, 2, N_NODES,      A2);   // a2
    layer(X0, 3, 3, N_NODES + 2,  T);    // g3 inner
    layer(T,  4, 4, N_NODES + 2,  A3);   // a3
    layer(X0, 5, 5, N_NODES + 20, T);    // g5 inner
    layer(T,  6, 6, N_NODES + 20, A4);   // a4

    // u = x @ (Wq Wk^T) + Wk bq  (replaces Q and all 5 K projections)
    prep_m1_kernel<<<cdiv(FDIM * FDIM, TPB), TPB>>>(Wq, Wk, bq);
    gemm_kernel<<<cdiv(N_NODES, 64), TPB>>>(X0, M1, V1, nullptr, nullptr,
                                            Ub, nullptr, nullptr, N_NODES);

    attn_kernel<<<cdiv(N_NODES * 32, TPB), TPB>>>(Wl, bl, (float*)d_out);
    (void)n_in; (void)out_size;
}

// round 12
// speedup vs baseline: 1.9711x; 1.2489x over previous
#include <cuda_runtime.h>
#include <math.h>
#include <stdint.h>

#define N_NODES 50000
#define FDIM    160
#define NMAX    50020   // N + S_EXTRA(20) padding rows; divisible by 4
#define NEDGE   500000
#define DKDIM   64
#define NGRAPH  7
#define OFFSTR  (NMAX + 4)   // per-graph offset stride, multiple of 4 ints (16B)

// ---------------- static device scratch (no runtime allocation) ----------------
__device__ float g_X0 [NMAX * FDIM];
__device__ float g_H  [NMAX * FDIM];
__device__ float g_T  [NMAX * FDIM];
__device__ float g_A1 [NMAX * FDIM];
__device__ float g_A2 [NMAX * FDIM];
__device__ float g_A3 [NMAX * FDIM];
__device__ float g_A4 [NMAX * FDIM];
__device__ float g_Ady[NMAX * FDIM];
__device__ float g_U  [N_NODES * FDIM];  // u = x @ (Wq Wk^T) + Wk bq
__device__ float g_M1 [FDIM * FDIM];
__device__ float g_v1 [FDIM];
__device__ float g_el [NMAX];
__device__ float g_er [NMAX];
__device__ __align__(16) int g_cntB [NGRAPH * NMAX];    // per-graph histogram
__device__ __align__(16) int g_curB [NGRAPH * NMAX];    // per-graph fill cursors
__device__ __align__(16) int g_offB [NGRAPH * OFFSTR];  // per-graph CSR offsets (padded stride)
__device__ int   g_ssrcB[NGRAPH * NEDGE];               // per-graph src sorted by dst

struct EdgePtrs { const int* src[NGRAPH]; const int* dst[NGRAPH]; };

// ---------------- helpers ----------------
__device__ __forceinline__ float warp_sum(float v) {
    #pragma unroll
    for (int o = 16; o > 0; o >>= 1) v += __shfl_xor_sync(0xffffffffu, v, o);
    return v;
}
__device__ __forceinline__ float warp_max(float v) {
    #pragma unroll
    for (int o = 16; o > 0; o >>= 1) v = fmaxf(v, __shfl_xor_sync(0xffffffffu, v, o));
    return v;
}

// tf32 split: hi = rna(x), lo = rna(x - hi); x - hi exact in fp32
__device__ __forceinline__ void tf32_split(float x, uint32_t& hi, uint32_t& lo) {
    asm("cvt.rna.tf32.f32 %0, %1;" : "=r"(hi) : "f"(x));
    float r = x - __uint_as_float(hi);
    asm("cvt.rna.tf32.f32 %0, %1;" : "=r"(lo) : "f"(r));
}

__device__ __forceinline__ void mma8(float acc[4], const uint32_t a[4],
                                     uint32_t b0, uint32_t b1) {
    asm volatile(
        "mma.sync.aligned.m16n8k8.row.col.f32.tf32.tf32.f32 "
        "{%0,%1,%2,%3}, {%4,%5,%6,%7}, {%8,%9}, {%0,%1,%2,%3};"
        : "+f"(acc[0]), "+f"(acc[1]), "+f"(acc[2]), "+f"(acc[3])
        : "r"(a[0]), "r"(a[1]), "r"(a[2]), "r"(a[3]), "r"(b0), "r"(b1));
}

// ---------------- batched CSR build ----------------
__global__ void batched_zero_kernel() {
    int i = blockIdx.x * blockDim.x + threadIdx.x;
    int n4 = NGRAPH * NMAX / 4;
    if (i < n4) {
        ((int4*)g_cntB)[i] = make_int4(0, 0, 0, 0);
        ((int4*)g_curB)[i] = make_int4(0, 0, 0, 0);
    }
}

__global__ void batched_hist_kernel(EdgePtrs ep) {
    int i = blockIdx.x * blockDim.x + threadIdx.x;
    if (i >= NGRAPH * NEDGE) return;
    int g = i / NEDGE, j = i - g * NEDGE;
    atomicAdd(&g_cntB[g * NMAX + ep.dst[g][j]], 1);
}

__global__ void batched_scan_kernel() {
    const int b = blockIdx.x;
    const int t = threadIdx.x;
    const int* cnt = g_cntB + b * NMAX;
    int* off = g_offB + b * OFFSTR;
    const int n4 = NMAX / 4;
    const int C4 = (n4 + 1023) / 1024;
    __shared__ int part[1024];

    int s = 0;
    for (int i = 0; i < C4; i++) {
        int idx = t * C4 + i;
        if (idx < n4) {
            int4 v = ((const int4*)cnt)[idx];
            s += v.x + v.y + v.z + v.w;
        }
    }
    part[t] = s;
    __syncthreads();
    for (int o = 1; o < 1024; o <<= 1) {
        int u = (t >= o) ? part[t - o] : 0;
        __syncthreads();
        part[t] += u;
        __syncthreads();
    }
    int run = part[t] - s;

    for (int i = 0; i < C4; i++) {
        int idx = t * C4 + i;
        if (idx < n4) {
            int4 v = ((const int4*)cnt)[idx];
            int4 o;
            o.x = run; run += v.x;
            o.y = run; run += v.y;
            o.z = run; run += v.z;
            o.w = run; run += v.w;
            ((int4*)off)[idx] = o;
        }
    }
    if (t == 1023) off[NMAX] = run;
}

__global__ void batched_fill_kernel(EdgePtrs ep) {
    int i = blockIdx.x * blockDim.x + threadIdx.x;
    if (i >= NGRAPH * NEDGE) return;
    int g = i / NEDGE, j = i - g * NEDGE;
    int d = ep.dst[g][j];
    int slot = g_offB[g * OFFSTR + d] + atomicAdd(&g_curB[g * NMAX + d], 1);
    g_ssrcB[g * NEDGE + slot] = ep.src[g][j];
}

// ---------------- TF32 tensor-core GEMM with 3-term split ----------------
// C[n x 160] = A[n x 160] @ B[160 x 160] (+bias)
// Optional fused epilogue: el[r] = C_noBias[r]·al, er[r] = C_noBias[r]·ar.
// 256 threads = 8 warps (4 along m x 2 along n); tile 64 x 160; mma m16n8k8.
__global__ __launch_bounds__(256)
void gemm_tc_kernel(const float* __restrict__ A, const float* __restrict__ B,
                    const float* __restrict__ bias,
                    const float* __restrict__ al, const float* __restrict__ ar,
                    float* __restrict__ C,
                    float* __restrict__ el, float* __restrict__ er, int n) {
    __shared__ float    As[64][20];          // pad 20: conflict-free frag loads
    __shared__ uint32_t BsHi[16][168];       // pre-split tf32 hi (pad 168)
    __shared__ uint32_t BsLo[16][168];       // pre-split tf32 lo
    __shared__ float    s_al[FDIM], s_ar[FDIM];
    __shared__ float    s_elr[2][2][64];     // [wn][el/er][row]

    const int tid  = threadIdx.x;
    const int wid  = tid >> 5;
    const int lane = tid & 31;
    const int wm   = wid & 3;                // warp row group (0..3)
    const int wn   = wid >> 2;               // warp col group (0..1)
    const int m0   = wm * 16;
    const int c0w  = wn * 80;
    const int row0 = blockIdx.x * 64;
    const int rl   = lane >> 2;              // groupID (0..7)
    const int kq   = lane & 3;               // threadID_in_group (0..3)

    if (al) {
        for (int i = tid; i < FDIM; i += 256) { s_al[i] = al[i]; s_ar[i] = ar[i]; }
    }

    float acc[10][4];
    #pragma unroll
    for (int s = 0; s < 10; s++)
        #pragma unroll
        for (int q = 0; q < 4; q++) acc[s][q] = 0.0f;

    for (int k0 = 0; k0 < FDIM; k0 += 16) {
        // stage A 64x16 (float4 per thread)
        {
            int m = tid >> 2, kc = (tid & 3) * 4;
            int r = row0 + m;
            float4 v = (r < n) ? *(const float4*)(A + (size_t)r * FDIM + k0 + kc)
                               : make_float4(0.f, 0.f, 0.f, 0.f);
            As[m][kc] = v.x; As[m][kc + 1] = v.y; As[m][kc + 2] = v.z; As[m][kc + 3] = v.w;
        }
        // stage B 16x160, pre-split into tf32 hi/lo
        for (int i = tid; i < 16 * 40; i += 256) {
            int k = i / 40, c4 = i - k * 40;
            float4 v = *(const float4*)(B + (size_t)(k0 + k) * FDIM + c4 * 4);
            uint32_t h0, l0, h1, l1, h2, l2, h3, l3;
            tf32_split(v.x, h0, l0); tf32_split(v.y, h1, l1);
            tf32_split(v.z, h2, l2); tf32_split(v.w, h3, l3);
            uint32_t* ph = &BsHi[k][c4 * 4];
            uint32_t* pl = &BsLo[k][c4 * 4];
            ph[0] = h0; ph[1] = h1; ph[2] = h2; ph[3] = h3;
            pl[0] = l0; pl[1] = l1; pl[2] = l2; pl[3] = l3;
        }
        __syncthreads();

        #pragma unroll
        for (int ks = 0; ks < 2; ks++) {
            const int kk = ks * 8;
            uint32_t ah[4], alo[4];
            tf32_split(As[m0 + rl][kk + kq],          ah[0], alo[0]);
            tf32_split(As[m0 + rl + 8][kk + kq],      ah[1], alo[1]);
            tf32_split(As[m0 + rl][kk + kq + 4],      ah[2], alo[2]);
            tf32_split(As[m0 + rl + 8][kk + kq + 4],  ah[3], alo[3]);
            #pragma unroll
            for (int s = 0; s < 10; s++) {
                const int cc = c0w + s * 8 + rl;
                uint32_t bh0 = BsHi[kk + kq][cc];
                uint32_t bh1 = BsHi[kk + kq + 4][cc];
                uint32_t bl0 = BsLo[kk + kq][cc];
                uint32_t bl1 = BsLo[kk + kq + 4][cc];
                mma8(acc[s], ah,  bh0, bh1);   // hi*hi
                mma8(acc[s], alo, bh0, bh1);   // lo*hi
                mma8(acc[s], ah,  bl0, bl1);   // hi*lo
            }
        }
        __syncthreads();
    }

    // write C (+bias); C frag: c0=(rl, 2kq), c1=(rl, 2kq+1), c2/c3 rows +8
    const int cq2 = kq * 2;
    {
        int ra = row0 + m0 + rl;
        int rb = ra + 8;
        #pragma unroll
        for (int s = 0; s < 10; s++) {
            int c = c0w + s * 8 + cq2;
            float b0v = bias ? bias[c] : 0.f;
            float b1v = bias ? bias[c + 1] : 0.f;
            if (ra < n) {
                C[(size_t)ra * FDIM + c]     = acc[s][0] + b0v;
                C[(size_t)ra * FDIM + c + 1] = acc[s][1] + b1v;
            }
            if (rb < n) {
                C[(size_t)rb * FDIM + c]     = acc[s][2] + b0v;
                C[(size_t)rb * FDIM + c + 1] = acc[s][3] + b1v;
            }
        }
    }

    // fused el/er epilogue from register accumulators
    if (al) {
        float pl0 = 0.f, pr0 = 0.f, pl1 = 0.f, pr1 = 0.f;
        #pragma unroll
        for (int s = 0; s < 10; s++) {
            int c = c0w + s * 8 + cq2;
            float w0 = s_al[c], w1 = s_al[c + 1];
            float v0 = s_ar[c], v1 = s_ar[c + 1];
            pl0 += acc[s][0] * w0 + acc[s][1] * w1;
            pr0 += acc[s][0] * v0 + acc[s][1] * v1;
            pl1 += acc[s][2] * w0 + acc[s][3] * w1;
            pr1 += acc[s][2] * v0 + acc[s][3] * v1;
        }
        #pragma unroll
        for (int o = 1; o <= 2; o <<= 1) {   // reduce over the 4 lanes of a quad row
            pl0 += __shfl_xor_sync(0xffffffffu, pl0, o);
            pr0 += __shfl_xor_sync(0xffffffffu, pr0, o);
            pl1 += __shfl_xor_sync(0xffffffffu, pl1, o);
            pr1 += __shfl_xor_sync(0xffffffffu, pr1, o);
        }
        if (kq == 0) {
            int ra = m0 + rl, rb = ra + 8;
            s_elr[wn][0][ra] = pl0; s_elr[wn][1][ra] = pr0;
            s_elr[wn][0][rb] = pl1; s_elr[wn][1][rb] = pr1;
        }
        __syncthreads();
        if (tid < 64) {
            int r = row0 + tid;
            if (r < n) {
                el[r] = s_elr[0][0][tid] + s_elr[1][0][tid];
                er[r] = s_elr[0][1][tid] + s_elr[1][1][tid];
            }
        }
    }
}

// ---------------- per-node kernels ----------------
__global__ void concat_kernel(const float* __restrict__ aft, const float* __restrict__ sta) {
    int idx = blockIdx.x * blockDim.x + threadIdx.x;
    if (idx >= NMAX * FDIM) return;
    int nd = idx / FDIM, f = idx % FDIM;
    float v = 0.0f;
    if (nd < N_NODES) v = (f < 144) ? aft[nd * 144 + f] : sta[nd * 16 + (f - 144)];
    g_X0[idx] = v;
}

// ---- fused edge-softmax + aggregation + bias + activation: one warp per node ----
__global__ void node_gather_kernel(const float* __restrict__ b, float* __restrict__ dest,
                                   int n, int gi) {
    int gid = blockIdx.x * blockDim.x + threadIdx.x;
    int w = gid >> 5;
    int lane = threadIdx.x & 31;
    if (w >= n) return;

    const int* off  = g_offB  + gi * OFFSTR;
    const int* ssrc = g_ssrcB + gi * NEDGE;
    const int start = off[w];
    const int end   = off[w + 1];
    const float er_d = g_er[w];

    float mi = -INFINITY, si = 0.f;
    for (int j = start + lane; j < end; j += 32) {
        float z = g_el[ssrc[j]] + er_d;
        z = (z > 0.f) ? z : 0.2f * z;
        if (z > mi) {
            si = si * expf(mi - z) + 1.0f;
            mi = z;
        } else {
            si += expf(z - mi);
        }
    }
    float mx = warp_max(mi);
    if (!isfinite(mx)) mx = 0.0f;
    float s = warp_sum(si * expf(mi - mx));
    const float inv = 1.0f / fmaxf(s, 1e-9f);

    float acc0 = 0.f, acc1 = 0.f, acc2 = 0.f, acc3 = 0.f, acc4 = 0.f;
    for (int g0 = start; g0 < end; g0 += 32) {
        int j = g0 + lane;
        int sN = 0; float wgt = 0.f;
        if (j < end) {
            sN = ssrc[j];
            float z = g_el[sN] + er_d;
            z = (z > 0.f) ? z : 0.2f * z;
            wgt = expf(z - mx) * inv;
        }
        int cnt = min(32, end - g0);
        for (int k = 0; k < cnt; k++) {
            float wk = __shfl_sync(0xffffffffu, wgt, k);
            int   sk = __shfl_sync(0xffffffffu, sN,  k);
            const float* hp = g_H + (size_t)sk * FDIM;
            acc0 += wk * hp[lane];
            acc1 += wk * hp[lane + 32];
            acc2 += wk * hp[lane + 64];
            acc3 += wk * hp[lane + 96];
            acc4 += wk * hp[lane + 128];
        }
    }

    float* od = dest + (size_t)w * FDIM;
    float v;
    v = acc0 + b[lane];       od[lane]       = (v > 0.f) ? v : 0.01f * v;
    v = acc1 + b[lane + 32];  od[lane + 32]  = (v > 0.f) ? v : 0.01f * v;
    v = acc2 + b[lane + 64];  od[lane + 64]  = (v > 0.f) ? v : 0.01f * v;
    v = acc3 + b[lane + 96];  od[lane + 96]  = (v > 0.f) ? v : 0.01f * v;
    v = acc4 + b[lane + 128]; od[lane + 128] = (v > 0.f) ? v : 0.01f * v;
}

// ---------------- precompute M1 = Wq @ Wk^T, v1 = Wk @ bq ----------------
__global__ void prep_m1_kernel(const float* __restrict__ Wq, const float* __restrict__ Wk,
                               const float* __restrict__ bq) {
    int idx = blockIdx.x * blockDim.x + threadIdx.x;
    if (idx < FDIM * FDIM) {
        int f = idx / FDIM, g = idx % FDIM;
        float s = 0.f;
        #pragma unroll 8
        for (int d = 0; d < DKDIM; d++) s += Wq[f * DKDIM + d] * Wk[g * DKDIM + d];
        g_M1[idx] = s;
    }
    if (idx < FDIM) {
        float s = 0.f;
        #pragma unroll 8
        for (int d = 0; d < DKDIM; d++) s += bq[d] * Wk[idx * DKDIM + d];
        g_v1[idx] = s;
    }
}

// ---------------- final attention merge + classifier + log_softmax ----------------
__global__ void attn_kernel(const float* __restrict__ Wl, const float* __restrict__ bl,
                            float* __restrict__ out) {
    int gid = blockIdx.x * blockDim.x + threadIdx.x;
    int w = gid >> 5;
    int lane = threadIdx.x & 31;
    if (w >= N_NODES) return;

    const float* ur = g_U + (size_t)w * FDIM;
    float u[5];
    #pragma unroll
    for (int t = 0; t < 5; t++) u[t] = ur[lane + 32 * t];

    const float* Ap[5] = { g_A1 + (size_t)w * FDIM, g_A2 + (size_t)w * FDIM,
                           g_A3 + (size_t)w * FDIM, g_A4 + (size_t)w * FDIM,
                           g_Ady + (size_t)w * FDIM };
    float a[5][5];
    #pragma unroll
    for (int j = 0; j < 5; j++)
        #pragma unroll
        for (int t = 0; t < 5; t++) a[j][t] = Ap[j][lane + 32 * t];

    float logit[5];
    #pragma unroll
    for (int j = 0; j < 5; j++) {
        float p = 0.f;
        #pragma unroll
        for (int t = 0; t < 5; t++) p += u[t] * a[j][t];
        logit[j] = warp_sum(p) * 0.125f;
    }

    float mx = logit[0];
    #pragma unroll
    for (int j = 1; j < 5; j++) mx = fmaxf(mx, logit[j]);
    float aw[5], asum = 0.f;
    #pragma unroll
    for (int j = 0; j < 5; j++) { aw[j] = expf(logit[j] - mx); asum += aw[j]; }
    float inv = 1.0f / asum;

    const float* xr = g_X0 + (size_t)w * FDIM;
    float y0 = 0.f, y1 = 0.f;
    #pragma unroll
    for (int t = 0; t < 5; t++) {
        int f = lane + 32 * t;
        float mf = 0.f;
        #pragma unroll
        for (int j = 0; j < 5; j++) mf += aw[j] * a[j][t];
        mf *= inv;
        float xv = xr[f];
        y0 += xv * Wl[2 * f]     + mf * Wl[2 * (160 + f)];
        y1 += xv * Wl[2 * f + 1] + mf * Wl[2 * (160 + f) + 1];
    }
    y0 = warp_sum(y0);
    y1 = warp_sum(y1);
    if (lane == 0) {
        y0 += bl[0]; y1 += bl[1];
        float m2 = fmaxf(y0, y1);
        float lz = m2 + logf(expf(y0 - m2) + expf(y1 - m2));
        out[2 * w]     = y0 - lz;
        out[2 * w + 1] = y1 - lz;
    }
}

// ---------------- host orchestration ----------------
static inline int cdiv(int a, int b) { return (a + b - 1) / b; }

extern "C" void kernel_launch(void* const* d_in, const int* in_sizes, int n_in,
                              void* d_out, int out_size) {
    bool sigOrder = (in_sizes[2] == 7 * FDIM * FDIM);
    int wbase = sigOrder ? 2 : 16;
    int ebase = sigOrder ? 12 : 2;

    const float* aft   = (const float*)d_in[0];
    const float* sta   = (const float*)d_in[1];
    const float* gat_W = (const float*)d_in[wbase + 0];
    const float* gat_al= (const float*)d_in[wbase + 1];
    const float* gat_ar= (const float*)d_in[wbase + 2];
    const float* gat_b = (const float*)d_in[wbase + 3];
    const float* Wq    = (const float*)d_in[wbase + 4];
    const float* bq    = (const float*)d_in[wbase + 5];
    const float* Wk    = (const float*)d_in[wbase + 6];
    const float* Wl    = (const float*)d_in[wbase + 8];
    const float* bl    = (const float*)d_in[wbase + 9];
    const int* e[14];
    for (int i = 0; i < 14; i++) e[i] = (const int*)d_in[ebase + i];

    void *pX0, *pT, *pA1, *pA2, *pA3, *pA4, *pAdy, *pU, *pM1, *pV1, *pH, *pEl, *pEr;
    cudaGetSymbolAddress(&pX0, g_X0);
    cudaGetSymbolAddress(&pT,  g_T);
    cudaGetSymbolAddress(&pA1, g_A1);
    cudaGetSymbolAddress(&pA2, g_A2);
    cudaGetSymbolAddress(&pA3, g_A3);
    cudaGetSymbolAddress(&pA4, g_A4);
    cudaGetSymbolAddress(&pAdy,g_Ady);
    cudaGetSymbolAddress(&pU,  g_U);
    cudaGetSymbolAddress(&pM1, g_M1);
    cudaGetSymbolAddress(&pV1, g_v1);
    cudaGetSymbolAddress(&pH,  g_H);
    cudaGetSymbolAddress(&pEl, g_el);
    cudaGetSymbolAddress(&pEr, g_er);
    float* X0  = (float*)pX0;
    float* T   = (float*)pT;
    float* A1  = (float*)pA1;
    float* A2  = (float*)pA2;
    float* A3  = (float*)pA3;
    float* A4  = (float*)pA4;
    float* Ady = (float*)pAdy;
    float* Ub  = (float*)pU;
    float* M1  = (float*)pM1;
    float* V1  = (float*)pV1;
    float* H   = (float*)pH;
    float* El  = (float*)pEl;
    float* Er  = (float*)pEr;

    const int TPB = 256;

    // batched CSR build for all 7 graphs up front (edge order: dy,1,2,3a,3b,4a,4b)
    EdgePtrs ep;
    for (int g = 0; g < NGRAPH; g++) { ep.src[g] = e[2 * g]; ep.dst[g] = e[2 * g + 1]; }
    batched_zero_kernel<<<cdiv(NGRAPH * NMAX / 4, TPB), TPB>>>();
    batched_hist_kernel<<<cdiv(NGRAPH * NEDGE, TPB), TPB>>>(ep);
    batched_scan_kernel<<<NGRAPH, 1024>>>();
    batched_fill_kernel<<<cdiv(NGRAPH * NEDGE, TPB), TPB>>>(ep);

    concat_kernel<<<cdiv(NMAX * FDIM, TPB), TPB>>>(aft, sta);

    auto layer = [&](const float* feats, int wi, int gi, int n, float* dest) {
        gemm_tc_kernel<<<cdiv(n, 64), TPB>>>(feats, gat_W + (size_t)wi * FDIM * FDIM,
                                             nullptr, gat_al + wi * FDIM, gat_ar + wi * FDIM,
                                             H, El, Er, n);
        node_gather_kernel<<<cdiv(n * 32, TPB), TPB>>>(gat_b + wi * FDIM, dest, n, gi);
    };

    layer(X0, 0, 0, N_NODES,      Ady);  // a_dy
    layer(X0, 1, 1, N_NODES,      A1);   // a1
    layer(X0, 2, 2, N_NODES,      A2);   // a2
    layer(X0, 3, 3, N_NODES + 2,  T);    // g3 inner
    layer(T,  4, 4, N_NODES + 2,  A3);   // a3
    layer(X0, 5, 5, N_NODES + 20, T);    // g5 inner
    layer(T,  6, 6, N_NODES + 20, A4);   // a4

    // u = x @ (Wq Wk^T) + Wk bq  (replaces Q and all 5 K projections)
    prep_m1_kernel<<<cdiv(FDIM * FDIM, TPB), TPB>>>(Wq, Wk, bq);
    gemm_tc_kernel<<<cdiv(N_NODES, 64), TPB>>>(X0, M1, V1, nullptr, nullptr,
                                               Ub, nullptr, nullptr, N_NODES);

    attn_kernel<<<cdiv(N_NODES * 32, TPB), TPB>>>(Wl, bl, (float*)d_out);
    (void)n_in; (void)out_size;
}

// round 13
// speedup vs baseline: 2.2179x; 1.1252x over previous
#include <cuda_runtime.h>
#include <math.h>
#include <stdint.h>

#define N_NODES 50000
#define FDIM    160
#define NMAX    50020   // N + S_EXTRA(20); divisible by 4
#define NEDGE   500000
#define DKDIM   64
#define NGRAPH  7
#define OFFSTR  (NMAX + 4)   // per-graph offset stride, 16B multiple

// ---------------- static device scratch (no runtime allocation) ----------------
__device__ float g_X0 [NMAX * FDIM];
__device__ float g_Hb [5][NMAX * FDIM];   // per-job GEMM outputs
__device__ float g_T3 [NMAX * FDIM];
__device__ float g_T5 [NMAX * FDIM];
__device__ float g_A1 [NMAX * FDIM];
__device__ float g_A2 [NMAX * FDIM];
__device__ float g_A3 [NMAX * FDIM];
__device__ float g_A4 [NMAX * FDIM];
__device__ float g_Ady[NMAX * FDIM];
__device__ float g_U  [NMAX * FDIM];
__device__ float g_M1 [FDIM * FDIM];
__device__ float g_v1 [FDIM];
__device__ float g_elB[5][NMAX];
__device__ float g_erB[5][NMAX];
__device__ __align__(16) int g_cntB [NGRAPH * NMAX];
__device__ __align__(16) int g_curB [NGRAPH * NMAX];
__device__ __align__(16) int g_offB [NGRAPH * OFFSTR];
__device__ int   g_ssrcB[NGRAPH * NEDGE];

struct EdgePtrs { const int* src[NGRAPH]; const int* dst[NGRAPH]; };

struct GemmJob {
    const float* A; const float* W; const float* bias;
    const float* al; const float* ar;
    float* C; float* el; float* er; int n;
};
struct GemmBatch { GemmJob j[5]; };

struct GatherJob {
    const float* b; const float* H; float* dest;
    const float* el; const float* er;
    const int* off; const int* ssrc; int n;
};
struct GatherBatch { GatherJob j[5]; };

// ---------------- helpers ----------------
__device__ __forceinline__ float warp_sum(float v) {
    #pragma unroll
    for (int o = 16; o > 0; o >>= 1) v += __shfl_xor_sync(0xffffffffu, v, o);
    return v;
}
__device__ __forceinline__ float warp_max(float v) {
    #pragma unroll
    for (int o = 16; o > 0; o >>= 1) v = fmaxf(v, __shfl_xor_sync(0xffffffffu, v, o));
    return v;
}

__device__ __forceinline__ void tf32_split(float x, uint32_t& hi, uint32_t& lo) {
    asm("cvt.rna.tf32.f32 %0, %1;" : "=r"(hi) : "f"(x));
    float r = x - __uint_as_float(hi);
    asm("cvt.rna.tf32.f32 %0, %1;" : "=r"(lo) : "f"(r));
}

__device__ __forceinline__ void mma8(float acc[4], const uint32_t a[4],
                                     uint32_t b0, uint32_t b1) {
    asm volatile(
        "mma.sync.aligned.m16n8k8.row.col.f32.tf32.tf32.f32 "
        "{%0,%1,%2,%3}, {%4,%5,%6,%7}, {%8,%9}, {%0,%1,%2,%3};"
        : "+f"(acc[0]), "+f"(acc[1]), "+f"(acc[2]), "+f"(acc[3])
        : "r"(a[0]), "r"(a[1]), "r"(a[2]), "r"(a[3]), "r"(b0), "r"(b1));
}

// ---------------- batched CSR build ----------------
__global__ void batched_zero_kernel() {
    int i = blockIdx.x * blockDim.x + threadIdx.x;
    int n4 = NGRAPH * NMAX / 4;
    if (i < n4) {
        ((int4*)g_cntB)[i] = make_int4(0, 0, 0, 0);
        ((int4*)g_curB)[i] = make_int4(0, 0, 0, 0);
    }
}

__global__ void batched_hist_kernel(EdgePtrs ep) {
    int i = blockIdx.x * blockDim.x + threadIdx.x;
    if (i >= NGRAPH * NEDGE) return;
    int g = i / NEDGE, j = i - g * NEDGE;
    atomicAdd(&g_cntB[g * NMAX + ep.dst[g][j]], 1);
}

__global__ void batched_scan_kernel() {
    const int b = blockIdx.x;
    const int t = threadIdx.x;
    const int* cnt = g_cntB + b * NMAX;
    int* off = g_offB + b * OFFSTR;
    const int n4 = NMAX / 4;
    const int C4 = (n4 + 1023) / 1024;
    __shared__ int part[1024];

    int s = 0;
    for (int i = 0; i < C4; i++) {
        int idx = t * C4 + i;
        if (idx < n4) {
            int4 v = ((const int4*)cnt)[idx];
            s += v.x + v.y + v.z + v.w;
        }
    }
    part[t] = s;
    __syncthreads();
    for (int o = 1; o < 1024; o <<= 1) {
        int u = (t >= o) ? part[t - o] : 0;
        __syncthreads();
        part[t] += u;
        __syncthreads();
    }
    int run = part[t] - s;

    for (int i = 0; i < C4; i++) {
        int idx = t * C4 + i;
        if (idx < n4) {
            int4 v = ((const int4*)cnt)[idx];
            int4 o;
            o.x = run; run += v.x;
            o.y = run; run += v.y;
            o.z = run; run += v.z;
            o.w = run; run += v.w;
            ((int4*)off)[idx] = o;
        }
    }
    if (t == 1023) off[NMAX] = run;
}

__global__ void batched_fill_kernel(EdgePtrs ep) {
    int i = blockIdx.x * blockDim.x + threadIdx.x;
    if (i >= NGRAPH * NEDGE) return;
    int g = i / NEDGE, j = i - g * NEDGE;
    int d = ep.dst[g][j];
    int slot = g_offB[g * OFFSTR + d] + atomicAdd(&g_curB[g * NMAX + d], 1);
    g_ssrcB[g * NEDGE + slot] = ep.src[g][j];
}

// ---------------- batched TF32 tensor-core GEMM (3-term split) ----------------
// blockIdx.y selects the job. Tile 64 x 160, 8 warps (4m x 2n), mma m16n8k8.
__global__ __launch_bounds__(256)
void gemm_tc_batched(GemmBatch gb) {
    const GemmJob jb = gb.j[blockIdx.y];
    const int n = jb.n;
    const int row0 = blockIdx.x * 64;
    if (row0 >= n) return;   // uniform per block

    __shared__ float    As[64][20];
    __shared__ uint32_t BsHi[16][168];
    __shared__ uint32_t BsLo[16][168];
    __shared__ float    s_al[FDIM], s_ar[FDIM];
    __shared__ float    s_elr[2][2][64];

    const float* __restrict__ A = jb.A;
    const float* __restrict__ B = jb.W;

    const int tid  = threadIdx.x;
    const int wid  = tid >> 5;
    const int lane = tid & 31;
    const int wm   = wid & 3;
    const int wn   = wid >> 2;
    const int m0   = wm * 16;
    const int c0w  = wn * 80;
    const int rl   = lane >> 2;
    const int kq   = lane & 3;

    if (jb.al) {
        for (int i = tid; i < FDIM; i += 256) { s_al[i] = jb.al[i]; s_ar[i] = jb.ar[i]; }
    }

    float acc[10][4];
    #pragma unroll
    for (int s = 0; s < 10; s++)
        #pragma unroll
        for (int q = 0; q < 4; q++) acc[s][q] = 0.0f;

    for (int k0 = 0; k0 < FDIM; k0 += 16) {
        {
            int m = tid >> 2, kc = (tid & 3) * 4;
            int r = row0 + m;
            float4 v = (r < n) ? *(const float4*)(A + (size_t)r * FDIM + k0 + kc)
                               : make_float4(0.f, 0.f, 0.f, 0.f);
            As[m][kc] = v.x; As[m][kc + 1] = v.y; As[m][kc + 2] = v.z; As[m][kc + 3] = v.w;
        }
        for (int i = tid; i < 16 * 40; i += 256) {
            int k = i / 40, c4 = i - k * 40;
            float4 v = *(const float4*)(B + (size_t)(k0 + k) * FDIM + c4 * 4);
            uint32_t h0, l0, h1, l1, h2, l2, h3, l3;
            tf32_split(v.x, h0, l0); tf32_split(v.y, h1, l1);
            tf32_split(v.z, h2, l2); tf32_split(v.w, h3, l3);
            uint32_t* ph = &BsHi[k][c4 * 4];
            uint32_t* pl = &BsLo[k][c4 * 4];
            ph[0] = h0; ph[1] = h1; ph[2] = h2; ph[3] = h3;
            pl[0] = l0; pl[1] = l1; pl[2] = l2; pl[3] = l3;
        }
        __syncthreads();

        #pragma unroll
        for (int ks = 0; ks < 2; ks++) {
            const int kk = ks * 8;
            uint32_t ah[4], alo[4];
            tf32_split(As[m0 + rl][kk + kq],          ah[0], alo[0]);
            tf32_split(As[m0 + rl + 8][kk + kq],      ah[1], alo[1]);
            tf32_split(As[m0 + rl][kk + kq + 4],      ah[2], alo[2]);
            tf32_split(As[m0 + rl + 8][kk + kq + 4],  ah[3], alo[3]);
            #pragma unroll
            for (int s = 0; s < 10; s++) {
                const int cc = c0w + s * 8 + rl;
                uint32_t bh0 = BsHi[kk + kq][cc];
                uint32_t bh1 = BsHi[kk + kq + 4][cc];
                uint32_t bl0 = BsLo[kk + kq][cc];
                uint32_t bl1 = BsLo[kk + kq + 4][cc];
                mma8(acc[s], ah,  bh0, bh1);
                mma8(acc[s], alo, bh0, bh1);
                mma8(acc[s], ah,  bl0, bl1);
            }
        }
        __syncthreads();
    }

    const int cq2 = kq * 2;
    {
        int ra = row0 + m0 + rl;
        int rb = ra + 8;
        #pragma unroll
        for (int s = 0; s < 10; s++) {
            int c = c0w + s * 8 + cq2;
            float b0v = jb.bias ? jb.bias[c] : 0.f;
            float b1v = jb.bias ? jb.bias[c + 1] : 0.f;
            if (ra < n) {
                jb.C[(size_t)ra * FDIM + c]     = acc[s][0] + b0v;
                jb.C[(size_t)ra * FDIM + c + 1] = acc[s][1] + b1v;
            }
            if (rb < n) {
                jb.C[(size_t)rb * FDIM + c]     = acc[s][2] + b0v;
                jb.C[(size_t)rb * FDIM + c + 1] = acc[s][3] + b1v;
            }
        }
    }

    if (jb.al) {
        float pl0 = 0.f, pr0 = 0.f, pl1 = 0.f, pr1 = 0.f;
        #pragma unroll
        for (int s = 0; s < 10; s++) {
            int c = c0w + s * 8 + cq2;
            float w0 = s_al[c], w1 = s_al[c + 1];
            float v0 = s_ar[c], v1 = s_ar[c + 1];
            pl0 += acc[s][0] * w0 + acc[s][1] * w1;
            pr0 += acc[s][0] * v0 + acc[s][1] * v1;
            pl1 += acc[s][2] * w0 + acc[s][3] * w1;
            pr1 += acc[s][2] * v0 + acc[s][3] * v1;
        }
        #pragma unroll
        for (int o = 1; o <= 2; o <<= 1) {
            pl0 += __shfl_xor_sync(0xffffffffu, pl0, o);
            pr0 += __shfl_xor_sync(0xffffffffu, pr0, o);
            pl1 += __shfl_xor_sync(0xffffffffu, pl1, o);
            pr1 += __shfl_xor_sync(0xffffffffu, pr1, o);
        }
        if (kq == 0) {
            int ra = m0 + rl, rb = ra + 8;
            s_elr[wn][0][ra] = pl0; s_elr[wn][1][ra] = pr0;
            s_elr[wn][0][rb] = pl1; s_elr[wn][1][rb] = pr1;
        }
        __syncthreads();
        if (tid < 64) {
            int r = row0 + tid;
            if (r < n) {
                jb.el[r] = s_elr[0][0][tid] + s_elr[1][0][tid];
                jb.er[r] = s_elr[0][1][tid] + s_elr[1][1][tid];
            }
        }
    }
}

// ---------------- per-node kernels ----------------
__global__ void concat_kernel(const float* __restrict__ aft, const float* __restrict__ sta) {
    int idx = blockIdx.x * blockDim.x + threadIdx.x;
    if (idx >= NMAX * FDIM) return;
    int nd = idx / FDIM, f = idx % FDIM;
    float v = 0.0f;
    if (nd < N_NODES) v = (f < 144) ? aft[nd * 144 + f] : sta[nd * 16 + (f - 144)];
    g_X0[idx] = v;
}

// ---- batched fused edge-softmax + aggregation: one warp per node, blockIdx.y = job ----
__global__ void gather_batched(GatherBatch gbt) {
    const GatherJob jb = gbt.j[blockIdx.y];
    int gid = blockIdx.x * blockDim.x + threadIdx.x;
    int w = gid >> 5;
    int lane = threadIdx.x & 31;
    if (w >= jb.n) return;

    const int start = jb.off[w];
    const int end   = jb.off[w + 1];
    const float er_d = jb.er[w];
    const float* __restrict__ elp = jb.el;
    const int* __restrict__ ssrc = jb.ssrc;
    const float* __restrict__ Hp = jb.H;

    float mi = -INFINITY, si = 0.f;
    for (int j = start + lane; j < end; j += 32) {
        float z = elp[ssrc[j]] + er_d;
        z = (z > 0.f) ? z : 0.2f * z;
        if (z > mi) {
            si = si * expf(mi - z) + 1.0f;
            mi = z;
        } else {
            si += expf(z - mi);
        }
    }
    float mx = warp_max(mi);
    if (!isfinite(mx)) mx = 0.0f;
    float s = warp_sum(si * expf(mi - mx));
    const float inv = 1.0f / fmaxf(s, 1e-9f);

    float acc0 = 0.f, acc1 = 0.f, acc2 = 0.f, acc3 = 0.f, acc4 = 0.f;
    for (int g0 = start; g0 < end; g0 += 32) {
        int j = g0 + lane;
        int sN = 0; float wgt = 0.f;
        if (j < end) {
            sN = ssrc[j];
            float z = elp[sN] + er_d;
            z = (z > 0.f) ? z : 0.2f * z;
            wgt = expf(z - mx) * inv;
        }
        int cnt = min(32, end - g0);
        for (int k = 0; k < cnt; k++) {
            float wk = __shfl_sync(0xffffffffu, wgt, k);
            int   sk = __shfl_sync(0xffffffffu, sN,  k);
            const float* hp = Hp + (size_t)sk * FDIM;
            acc0 += wk * hp[lane];
            acc1 += wk * hp[lane + 32];
            acc2 += wk * hp[lane + 64];
            acc3 += wk * hp[lane + 96];
            acc4 += wk * hp[lane + 128];
        }
    }

    float* od = jb.dest + (size_t)w * FDIM;
    const float* b = jb.b;
    float v;
    v = acc0 + b[lane];       od[lane]       = (v > 0.f) ? v : 0.01f * v;
    v = acc1 + b[lane + 32];  od[lane + 32]  = (v > 0.f) ? v : 0.01f * v;
    v = acc2 + b[lane + 64];  od[lane + 64]  = (v > 0.f) ? v : 0.01f * v;
    v = acc3 + b[lane + 96];  od[lane + 96]  = (v > 0.f) ? v : 0.01f * v;
    v = acc4 + b[lane + 128]; od[lane + 128] = (v > 0.f) ? v : 0.01f * v;
}

// ---------------- precompute M1 = Wq @ Wk^T, v1 = Wk @ bq ----------------
__global__ void prep_m1_kernel(const float* __restrict__ Wq, const float* __restrict__ Wk,
                               const float* __restrict__ bq) {
    int idx = blockIdx.x * blockDim.x + threadIdx.x;
    if (idx < FDIM * FDIM) {
        int f = idx / FDIM, g = idx % FDIM;
        float s = 0.f;
        #pragma unroll 8
        for (int d = 0; d < DKDIM; d++) s += Wq[f * DKDIM + d] * Wk[g * DKDIM + d];
        g_M1[idx] = s;
    }
    if (idx < FDIM) {
        float s = 0.f;
        #pragma unroll 8
        for (int d = 0; d < DKDIM; d++) s += bq[d] * Wk[idx * DKDIM + d];
        g_v1[idx] = s;
    }
}

// ---------------- final attention merge + classifier + log_softmax ----------------
__global__ void attn_kernel(const float* __restrict__ Wl, const float* __restrict__ bl,
                            float* __restrict__ out) {
    int gid = blockIdx.x * blockDim.x + threadIdx.x;
    int w = gid >> 5;
    int lane = threadIdx.x & 31;
    if (w >= N_NODES) return;

    const float* ur = g_U + (size_t)w * FDIM;
    float u[5];
    #pragma unroll
    for (int t = 0; t < 5; t++) u[t] = ur[lane + 32 * t];

    const float* Ap[5] = { g_A1 + (size_t)w * FDIM, g_A2 + (size_t)w * FDIM,
                           g_A3 + (size_t)w * FDIM, g_A4 + (size_t)w * FDIM,
                           g_Ady + (size_t)w * FDIM };
    float a[5][5];
    #pragma unroll
    for (int j = 0; j < 5; j++)
        #pragma unroll
        for (int t = 0; t < 5; t++) a[j][t] = Ap[j][lane + 32 * t];

    float logit[5];
    #pragma unroll
    for (int j = 0; j < 5; j++) {
        float p = 0.f;
        #pragma unroll
        for (int t = 0; t < 5; t++) p += u[t] * a[j][t];
        logit[j] = warp_sum(p) * 0.125f;
    }

    float mx = logit[0];
    #pragma unroll
    for (int j = 1; j < 5; j++) mx = fmaxf(mx, logit[j]);
    float aw[5], asum = 0.f;
    #pragma unroll
    for (int j = 0; j < 5; j++) { aw[j] = expf(logit[j] - mx); asum += aw[j]; }
    float inv = 1.0f / asum;

    const float* xr = g_X0 + (size_t)w * FDIM;
    float y0 = 0.f, y1 = 0.f;
    #pragma unroll
    for (int t = 0; t < 5; t++) {
        int f = lane + 32 * t;
        float mf = 0.f;
        #pragma unroll
        for (int j = 0; j < 5; j++) mf += aw[j] * a[j][t];
        mf *= inv;
        float xv = xr[f];
        y0 += xv * Wl[2 * f]     + mf * Wl[2 * (160 + f)];
        y1 += xv * Wl[2 * f + 1] + mf * Wl[2 * (160 + f) + 1];
    }
    y0 = warp_sum(y0);
    y1 = warp_sum(y1);
    if (lane == 0) {
        y0 += bl[0]; y1 += bl[1];
        float m2 = fmaxf(y0, y1);
        float lz = m2 + logf(expf(y0 - m2) + expf(y1 - m2));
        out[2 * w]     = y0 - lz;
        out[2 * w + 1] = y1 - lz;
    }
}

// ---------------- host orchestration ----------------
static inline int cdiv(int a, int b) { return (a + b - 1) / b; }

extern "C" void kernel_launch(void* const* d_in, const int* in_sizes, int n_in,
                              void* d_out, int out_size) {
    bool sigOrder = (in_sizes[2] == 7 * FDIM * FDIM);
    int wbase = sigOrder ? 2 : 16;
    int ebase = sigOrder ? 12 : 2;

    const float* aft   = (const float*)d_in[0];
    const float* sta   = (const float*)d_in[1];
    const float* gat_W = (const float*)d_in[wbase + 0];
    const float* gat_al= (const float*)d_in[wbase + 1];
    const float* gat_ar= (const float*)d_in[wbase + 2];
    const float* gat_b = (const float*)d_in[wbase + 3];
    const float* Wq    = (const float*)d_in[wbase + 4];
    const float* bq    = (const float*)d_in[wbase + 5];
    const float* Wk    = (const float*)d_in[wbase + 6];
    const float* Wl    = (const float*)d_in[wbase + 8];
    const float* bl    = (const float*)d_in[wbase + 9];
    const int* e[14];
    for (int i = 0; i < 14; i++) e[i] = (const int*)d_in[ebase + i];

    void *pX0, *pHb, *pT3, *pT5, *pA1, *pA2, *pA3, *pA4, *pAdy, *pU, *pM1, *pV1,
         *pElB, *pErB, *pOff, *pSrc;
    cudaGetSymbolAddress(&pX0, g_X0);
    cudaGetSymbolAddress(&pHb, g_Hb);
    cudaGetSymbolAddress(&pT3, g_T3);
    cudaGetSymbolAddress(&pT5, g_T5);
    cudaGetSymbolAddress(&pA1, g_A1);
    cudaGetSymbolAddress(&pA2, g_A2);
    cudaGetSymbolAddress(&pA3, g_A3);
    cudaGetSymbolAddress(&pA4, g_A4);
    cudaGetSymbolAddress(&pAdy,g_Ady);
    cudaGetSymbolAddress(&pU,  g_U);
    cudaGetSymbolAddress(&pM1, g_M1);
    cudaGetSymbolAddress(&pV1, g_v1);
    cudaGetSymbolAddress(&pElB,g_elB);
    cudaGetSymbolAddress(&pErB,g_erB);
    cudaGetSymbolAddress(&pOff,g_offB);
    cudaGetSymbolAddress(&pSrc,g_ssrcB);

    float* X0  = (float*)pX0;
    float* T3  = (float*)pT3;
    float* T5  = (float*)pT5;
    float* A1  = (float*)pA1;
    float* A2  = (float*)pA2;
    float* A3  = (float*)pA3;
    float* A4  = (float*)pA4;
    float* Ady = (float*)pAdy;
    float* Ub  = (float*)pU;
    float* M1  = (float*)pM1;
    float* V1  = (float*)pV1;
    auto Hbuf = [&](int i) { return (float*)pHb + (size_t)i * NMAX * FDIM; };
    auto ElB  = [&](int i) { return (float*)pElB + (size_t)i * NMAX; };
    auto ErB  = [&](int i) { return (float*)pErB + (size_t)i * NMAX; };
    auto Off  = [&](int g) { return (int*)pOff + (size_t)g * OFFSTR; };
    auto Ssrc = [&](int g) { return (int*)pSrc + (size_t)g * NEDGE; };

    const int TPB = 256;
    const int GX = cdiv(NMAX, 64);              // 782 row-tiles (max n)
    const int GW = cdiv(NMAX * 32, TPB);        // gather warps grid

    EdgePtrs ep;
    for (int g = 0; g < NGRAPH; g++) { ep.src[g] = e[2 * g]; ep.dst[g] = e[2 * g + 1]; }

    // layer n sizes and graph mapping: layer i uses graph i (dy,1,2,3a,3b,4a,4b)
    int nL[7] = { N_NODES, N_NODES, N_NODES, N_NODES + 2, N_NODES + 2,
                  N_NODES + 20, N_NODES + 20 };

    // ---- launch 0..2: zero, hist, concat ----
    batched_zero_kernel<<<cdiv(NGRAPH * NMAX / 4, TPB), TPB>>>();
    batched_hist_kernel<<<cdiv(NGRAPH * NEDGE, TPB), TPB>>>(ep);
    concat_kernel<<<cdiv(NMAX * FDIM, TPB), TPB>>>(aft, sta);

    // ---- launch 3: batched GEMM A — layers {0,1,2,3,5} from X0 (ncu target) ----
    GemmBatch ga;
    int laA[5] = { 0, 1, 2, 3, 5 };
    for (int k = 0; k < 5; k++) {
        int wi = laA[k];
        ga.j[k] = { X0, gat_W + (size_t)wi * FDIM * FDIM, nullptr,
                    gat_al + wi * FDIM, gat_ar + wi * FDIM,
                    Hbuf(k), ElB(k), ErB(k), nL[wi] };
    }
    gemm_tc_batched<<<dim3(GX, 5), TPB>>>(ga);

    // ---- launch 4: prep M1/v1 ----
    prep_m1_kernel<<<cdiv(FDIM * FDIM, TPB), TPB>>>(Wq, Wk, bq);

    // ---- launch 5..6: scan, fill ----
    batched_scan_kernel<<<NGRAPH, 1024>>>();
    batched_fill_kernel<<<cdiv(NGRAPH * NEDGE, TPB), TPB>>>(ep);

    // ---- launch 7: batched gather A ----
    GatherBatch gta;
    float* destA[5] = { Ady, A1, A2, T3, T5 };
    for (int k = 0; k < 5; k++) {
        int wi = laA[k];
        gta.j[k] = { gat_b + wi * FDIM, Hbuf(k), destA[k],
                     ElB(k), ErB(k), Off(wi), Ssrc(wi), nL[wi] };
    }
    gather_batched<<<dim3(GW, 5), TPB>>>(gta);

    // ---- launch 8: batched GEMM B — layers {4,6} + U projection ----
    GemmBatch gbB;
    gbB.j[0] = { T3, gat_W + (size_t)4 * FDIM * FDIM, nullptr,
                 gat_al + 4 * FDIM, gat_ar + 4 * FDIM,
                 Hbuf(0), ElB(0), ErB(0), nL[4] };
    gbB.j[1] = { T5, gat_W + (size_t)6 * FDIM * FDIM, nullptr,
                 gat_al + 6 * FDIM, gat_ar + 6 * FDIM,
                 Hbuf(1), ElB(1), ErB(1), nL[6] };
    gbB.j[2] = { X0, M1, V1, nullptr, nullptr, Ub, nullptr, nullptr, N_NODES };
    gbB.j[3] = gbB.j[2];  // unused padding (grid.y = 3)
    gbB.j[4] = gbB.j[2];
    gemm_tc_batched<<<dim3(GX, 3), TPB>>>(gbB);

    // ---- launch 9: batched gather B ----
    GatherBatch gtb;
    gtb.j[0] = { gat_b + 4 * FDIM, Hbuf(0), A3, ElB(0), ErB(0), Off(4), Ssrc(4), nL[4] };
    gtb.j[1] = { gat_b + 6 * FDIM, Hbuf(1), A4, ElB(1), ErB(1), Off(6), Ssrc(6), nL[6] };
    gtb.j[2] = gtb.j[0];  // unused padding
    gtb.j[3] = gtb.j[0];
    gtb.j[4] = gtb.j[0];
    gather_batched<<<dim3(GW, 2), TPB>>>(gtb);

    // ---- launch 10: attention merge + classifier ----
    attn_kernel<<<cdiv(N_NODES * 32, TPB), TPB>>>(Wl, bl, (float*)d_out);
    (void)n_in; (void)out_size;
}